// round 9
// baseline (speedup 1.0000x reference)
#include <cuda_runtime.h>
#include <cuda_fp16.h>
#include <math.h>
#include <stdint.h>

#define HIDDEN 1024
#define HEADS 16
#define HEADD 64
#define LAYERS 4
#define MLPD 4096
#define NTOK 1568
#define BATCH 2
#define ROWS (BATCH * NTOK)          // 3136
#define PATCH_K 1536                 // 3*2*16*16
#define MEG (1 << 20)

// ---------------- scratch (device globals; no allocation allowed) ----------------
__device__ float  g_h  [ROWS * HIDDEN];
__device__ float  g_q  [ROWS * HIDDEN];
__device__ float  g_k  [ROWS * HIDDEN];
__device__ __half g_qh  [ROWS * HIDDEN];
__device__ __half g_kh  [ROWS * HIDDEN];
__device__ __half g_vh  [ROWS * HIDDEN];
__device__ __half g_xnh [ROWS * HIDDEN];
__device__ __half g_aoh [ROWS * HIDDEN];
__device__ __half g_mlph[ROWS * MLPD];
__device__ __half g_colh[ROWS * PATCH_K];
__device__ __half g_wrh [12 * MEG];   // per-layer fp16 weights (or patch embed)

__device__ __forceinline__ uint32_t pack2(float a, float b) {
    __half2 h = __floats2half2_rn(a, b);
    return *(uint32_t*)&h;
}

// ---------------- weight conversion to fp16 ----------------
__global__ void round4_k(const float* __restrict__ in, __half* __restrict__ out, int n4) {
    int i = blockIdx.x * 256 + threadIdx.x;
    if (i >= n4) return;
    float4 v = ((const float4*)in)[i];
    ((uint2*)out)[i] = make_uint2(pack2(v.x, v.y), pack2(v.z, v.w));
}

__global__ void round_layer_k(const float* __restrict__ qw, const float* __restrict__ kw,
                              const float* __restrict__ vw, const float* __restrict__ pw,
                              const float* __restrict__ f1, const float* __restrict__ f2,
                              __half* __restrict__ out) {
    int i = blockIdx.x * 256 + threadIdx.x;      // float4 index, total 3*2^20
    if (i >= 3 * MEG) return;
    int u = i >> 18;
    const float* src;
    int base;
    if (u < 4) {
        src = (u == 0) ? qw : (u == 1) ? kw : (u == 2) ? vw : pw;
        base = i & 262143;
    } else if (u < 8) { src = f1; base = i - 4 * 262144; }
    else             { src = f2; base = i - 8 * 262144; }
    float4 v = ((const float4*)src)[base];
    ((uint2*)out)[i] = make_uint2(pack2(v.x, v.y), pack2(v.z, v.w));
}

// ---------------- im2col (stores fp16) ----------------
__global__ void im2col_k(const float* __restrict__ px, __half* __restrict__ col) {
    int idx = blockIdx.x * 256 + threadIdx.x;
    if (idx >= ROWS * PATCH_K) return;
    int m = idx / PATCH_K;
    int j = idx - m * PATCH_K;
    int c  = j >> 9;
    int r  = j & 511;
    int t  = r >> 8;
    int ph = (r >> 4) & 15;
    int pw = r & 15;
    int b = m / NTOK;
    int n = m - b * NTOK;
    int d  = n / 196;
    int rr = n - d * 196;
    int hy = rr / 14;
    int wx = rr - hy * 14;
    size_t src = ((size_t)((b * 16 + d * 2 + t) * 3 + c)) * (224 * 224)
               + (size_t)(hy * 16 + ph) * 224 + (wx * 16 + pw);
    col[idx] = __float2half_rn(px[src]);
}

// ---------------- fp16 tensor-core GEMM (m16n8k16, fp32 accum) ----------------
// CTA 128x128, 4 warps, warp tile 64x64 (2x2 warp grid).
// MODE 0: bias, 1: bias+gelu -> half out, 2: bias+residual, 3: fused QKV (V -> half)
__device__ __forceinline__ void mma16(float* c, uint32_t a0, uint32_t a1, uint32_t a2,
                                      uint32_t a3, uint32_t b0, uint32_t b1) {
    asm volatile(
        "mma.sync.aligned.m16n8k16.row.col.f32.f16.f16.f32 "
        "{%0,%1,%2,%3},{%4,%5,%6,%7},{%8,%9},{%0,%1,%2,%3};"
        : "+f"(c[0]), "+f"(c[1]), "+f"(c[2]), "+f"(c[3])
        : "r"(a0), "r"(a1), "r"(a2), "r"(a3), "r"(b0), "r"(b1));
}

#define GRP_PAIRS 513
#define BUF_U32   (4 * GRP_PAIRS * 2)        // 4104
#define DBUF_U32  (2 * BUF_U32)              // A+B per stage: 8208
#define GEMM_SMEM (2 * DBUF_U32 * 4)         // bytes: 65664

template <int MODE>
__global__ __launch_bounds__(128, 2) void tgemm(
    const __half* __restrict__ A,
    const __half* __restrict__ B0, const __half* __restrict__ B1, const __half* __restrict__ B2,
    const float* __restrict__ bias0, const float* __restrict__ bias1, const float* __restrict__ bias2,
    const float* __restrict__ res, float* __restrict__ C0, float* __restrict__ C1,
    float* __restrict__ C2, int M, int N, int K)
{
    extern __shared__ uint32_t smu[];
    int m0 = blockIdx.y * 128;
    int n0 = blockIdx.x * 128;
    const __half* B = B0;
    const float* bias = bias0;
    float* C = C0;
    int wsel = 0;
    if (MODE == 3) {
        wsel = n0 >> 10;
        if (wsel == 1) { B = B1; bias = bias1; C = C1; }
        else if (wsel == 2) { B = B2; bias = bias2; C = C2; }
        n0 &= 1023;
    }

    const int t = threadIdx.x;
    const int quad = t & 7;          // which uint4 (8 halves) of the 64-half chunk
    const int rbase = t >> 3;        // 0..15
    const int g8l = quad >> 1;       // k16-group 0..3
    const int half_s = quad & 1;     // lo/hi slot of pair
    const int warp = t >> 5, lane = t & 31;
    const int wm = (warp >> 1) * 64, wn = (warp & 1) * 64;
    const int g = lane >> 2, tig = lane & 3;

    float acc[4][8][4];
#pragma unroll
    for (int i = 0; i < 4; i++)
#pragma unroll
        for (int j = 0; j < 8; j++)
#pragma unroll
            for (int q = 0; q < 4; q++) acc[i][j][q] = 0.f;

    const int NC = K >> 6;           // 64 halves per chunk

    // prologue: stage chunk 0 (8 rows per thread per operand)
    {
        uint32_t* da = smu + g8l * (GRP_PAIRS * 2) + half_s;
        uint32_t* db = da + BUF_U32;
#pragma unroll
        for (int p = 0; p < 8; p++) {
            int gm = m0 + p * 16 + rbase;
            uint4 va = (gm < M) ? *(const uint4*)&A[(size_t)gm * K + quad * 8]
                                : make_uint4(0u, 0u, 0u, 0u);
            uint32_t* d = da + (p * 16 + rbase) * 8;
            d[0] = va.x; d[2] = va.y; d[4] = va.z; d[6] = va.w;
            int gn = n0 + p * 16 + rbase;
            uint4 vb = *(const uint4*)&B[(size_t)gn * K + quad * 8];
            uint32_t* e = db + (p * 16 + rbase) * 8;
            e[0] = vb.x; e[2] = vb.y; e[4] = vb.z; e[6] = vb.w;
        }
    }
    __syncthreads();

    for (int c = 0; c < NC; c++) {
        const uint32_t* a = smu + (c & 1) * DBUF_U32;
        const uint32_t* bsh = a + BUF_U32;
        bool more = (c + 1 < NC);
        int k0n = (c + 1) << 6;
        uint32_t* da = smu + ((c + 1) & 1) * DBUF_U32 + g8l * (GRP_PAIRS * 2) + half_s;
        uint32_t* db = da + BUF_U32;

        auto comp = [&](int gg) {
            uint2 pa[4][2];
            uint2 pb[8];
#pragma unroll
            for (int fm = 0; fm < 4; fm++) {
                int r = wm + fm * 16 + g;
                pa[fm][0] = *(const uint2*)&a[(gg * GRP_PAIRS + r * 4 + tig) * 2];
                pa[fm][1] = *(const uint2*)&a[(gg * GRP_PAIRS + (r + 8) * 4 + tig) * 2];
            }
#pragma unroll
            for (int fn = 0; fn < 8; fn++) {
                int ci = wn + fn * 8 + g;
                pb[fn] = *(const uint2*)&bsh[(gg * GRP_PAIRS + ci * 4 + tig) * 2];
            }
#pragma unroll
            for (int fm = 0; fm < 4; fm++)
#pragma unroll
                for (int fn = 0; fn < 8; fn++)
                    mma16(acc[fm][fn], pa[fm][0].x, pa[fm][1].x, pa[fm][0].y, pa[fm][1].y,
                          pb[fn].x, pb[fn].y);
        };
        auto lda = [&](int p) -> uint4 {
            int gm = m0 + p * 16 + rbase;
            return (gm < M) ? *(const uint4*)&A[(size_t)gm * K + k0n + quad * 8]
                            : make_uint4(0u, 0u, 0u, 0u);
        };
        auto ldb = [&](int p) -> uint4 {
            int gn = n0 + p * 16 + rbase;
            return *(const uint4*)&B[(size_t)gn * K + k0n + quad * 8];
        };
        auto sta = [&](uint4 v, int p) {
            uint32_t* d = da + (p * 16 + rbase) * 8;
            d[0] = v.x; d[2] = v.y; d[4] = v.z; d[6] = v.w;
        };
        auto stb = [&](uint4 v, int p) {
            uint32_t* d = db + (p * 16 + rbase) * 8;
            d[0] = v.x; d[2] = v.y; d[4] = v.z; d[6] = v.w;
        };

        uint4 ra[4], rb[4];
        comp(0);
        if (more) {
            ra[0] = lda(0); ra[1] = lda(1); ra[2] = lda(2); ra[3] = lda(3);
            rb[0] = ldb(0); rb[1] = ldb(1); rb[2] = ldb(2); rb[3] = ldb(3);
        }
        comp(1);
        if (more) {
            sta(ra[0], 0); sta(ra[1], 1); sta(ra[2], 2); sta(ra[3], 3);
            ra[0] = lda(4); ra[1] = lda(5); ra[2] = lda(6); ra[3] = lda(7);
        }
        comp(2);
        if (more) {
            stb(rb[0], 0); stb(rb[1], 1); stb(rb[2], 2); stb(rb[3], 3);
            rb[0] = ldb(4); rb[1] = ldb(5); rb[2] = ldb(6); rb[3] = ldb(7);
        }
        comp(3);
        if (more) {
            sta(ra[0], 4); sta(ra[1], 5); sta(ra[2], 6); sta(ra[3], 7);
            stb(rb[0], 4); stb(rb[1], 5); stb(rb[2], 6); stb(rb[3], 7);
        }
        __syncthreads();
    }

    // epilogue
    __half* Ch = (__half*)C;
    bool hstore = (MODE == 1) || (MODE == 3 && wsel == 2);
#pragma unroll
    for (int fm = 0; fm < 4; fm++) {
        int r0 = m0 + wm + fm * 16 + g;
#pragma unroll
        for (int fn = 0; fn < 8; fn++) {
            int col = n0 + wn + fn * 8 + 2 * tig;
            float b0v = bias[col], b1v = bias[col + 1];
#pragma unroll
            for (int hrow = 0; hrow < 2; hrow++) {
                int r = r0 + hrow * 8;
                if (r >= M) continue;
                float v0 = acc[fm][fn][hrow * 2 + 0] + b0v;
                float v1 = acc[fm][fn][hrow * 2 + 1] + b1v;
                if (MODE == 1) {
                    v0 = 0.5f * v0 * (1.f + erff(v0 * 0.70710678118654752f));
                    v1 = 0.5f * v1 * (1.f + erff(v1 * 0.70710678118654752f));
                }
                if (hstore) {
                    *(uint32_t*)&Ch[(size_t)r * N + col] = pack2(v0, v1);
                } else {
                    if (MODE == 2) {
                        const float* rr = &res[(size_t)r * N + col];
                        v0 += rr[0]; v1 += rr[1];
                    }
                    *(float2*)&C[(size_t)r * N + col] = make_float2(v0, v1);
                }
            }
        }
    }
}

// ---------------- LayerNorm (HALF_OUT: write fp16 for GEMM input) ----------------
template <bool HALF_OUT>
__global__ __launch_bounds__(256) void ln_k(
    const float* __restrict__ x, const float* __restrict__ g,
    const float* __restrict__ b, void* __restrict__ yv)
{
    __shared__ float red[8];
    __shared__ float stat[2];
    int row = blockIdx.x, tid = threadIdx.x;
    const float* xr = x + (size_t)row * HIDDEN;
    float v[4];
    float s = 0.f;
#pragma unroll
    for (int i = 0; i < 4; i++) { v[i] = xr[tid + i * 256]; s += v[i]; }
#pragma unroll
    for (int o = 16; o > 0; o >>= 1) s += __shfl_xor_sync(~0u, s, o);
    if ((tid & 31) == 0) red[tid >> 5] = s;
    __syncthreads();
    if (tid < 32) {
        float t = (tid < 8) ? red[tid] : 0.f;
#pragma unroll
        for (int o = 4; o > 0; o >>= 1) t += __shfl_xor_sync(~0u, t, o);
        if (tid == 0) stat[0] = t * (1.f / HIDDEN);
    }
    __syncthreads();
    float mu = stat[0];
    float s2 = 0.f;
#pragma unroll
    for (int i = 0; i < 4; i++) { float d = v[i] - mu; s2 += d * d; }
#pragma unroll
    for (int o = 16; o > 0; o >>= 1) s2 += __shfl_xor_sync(~0u, s2, o);
    if ((tid & 31) == 0) red[tid >> 5] = s2;
    __syncthreads();
    if (tid < 32) {
        float t = (tid < 8) ? red[tid] : 0.f;
#pragma unroll
        for (int o = 4; o > 0; o >>= 1) t += __shfl_xor_sync(~0u, t, o);
        if (tid == 0) stat[1] = rsqrtf(t * (1.f / HIDDEN) + 1e-6f);
    }
    __syncthreads();
    float rs = stat[1];
#pragma unroll
    for (int i = 0; i < 4; i++) {
        int c = tid + i * 256;
        float o = (v[i] - mu) * rs * g[c] + b[c];
        if (HALF_OUT) ((__half*)yv)[(size_t)row * HIDDEN + c] = __float2half_rn(o);
        else          ((float*)yv)[(size_t)row * HIDDEN + c] = o;
    }
}

// ---------------- RoPE: fp32 q/k in -> fp16 q (pre-scaled 1/8) / k out ----------
__global__ void rope_h(const float* __restrict__ q, const float* __restrict__ k,
                       __half* __restrict__ qh, __half* __restrict__ kh) {
    int idx = blockIdx.x * 256 + threadIdx.x;
    const int TOTAL = ROWS * HEADS * 32;
    if (idx >= TOTAL) return;
    int j = idx & 31;                // pair index within head dim (2*j, 2*j+1)
    int t = idx >> 5;
    int h = t & 15;
    int bn = t >> 4;
    size_t base = (size_t)bn * HIDDEN + h * HEADD + 2 * j;
    float x0 = q[base], x1 = q[base + 1];
    float y0 = k[base], y1 = k[base + 1];
    if (j < 30) {
        int n = bn % NTOK;
        int a = j / 10, i = j - a * 10;
        int dpos = n / 196, r = n - dpos * 196;
        int pos = (a == 0) ? dpos : (a == 1) ? (r / 14) : (r % 14);
        int i0 = (2 * i) % 10, i1 = (2 * i + 1) % 10;
        const float LN1E4_O10 = 0.92103403719761840f;
        float f0 = (float)pos * expf(-LN1E4_O10 * (float)i0);
        float f1 = (float)pos * expf(-LN1E4_O10 * (float)i1);
        float s0, c0, s1, c1;
        sincosf(f0, &s0, &c0);
        sincosf(f1, &s1, &c1);
        float nq0 = x0 * c0 - x1 * s0;
        float nq1 = x1 * c1 + x0 * s1;
        float nk0 = y0 * c0 - y1 * s0;
        float nk1 = y1 * c1 + y0 * s1;
        x0 = nq0; x1 = nq1; y0 = nk0; y1 = nk1;
    }
    *(uint32_t*)&qh[base] = pack2(x0 * 0.125f, x1 * 0.125f);
    *(uint32_t*)&kh[base] = pack2(y0, y1);
}

// ---------------- Flash attention, fp16 m16n8k16 ----------------
#define KST2 36   // u32 row stride (72 halves); 36 % 32 == 4 -> conflict-free frags
#define VST2 36
#define PST2 36

__global__ __launch_bounds__(128) void attn_h(
    const __half* __restrict__ Q, const __half* __restrict__ K,
    const __half* __restrict__ V, __half* __restrict__ O)
{
    __shared__ uint32_t Ks[64 * KST2];
    __shared__ uint32_t Vs[64 * VST2];
    __shared__ uint32_t Ps[64 * PST2];

    int b = blockIdx.y >> 4, h = blockIdx.y & 15;
    int q0 = blockIdx.x * 64;
    int tid = threadIdx.x, w = tid >> 5, lane = tid & 31;
    int g = lane >> 2, tq = lane & 3;

    const __half* Qb = Q + (size_t)b * NTOK * HIDDEN + h * HEADD;
    const __half* Kb = K + (size_t)b * NTOK * HIDDEN + h * HEADD;
    const __half* Vb = V + (size_t)b * NTOK * HIDDEN + h * HEADD;

    uint32_t qa[4][4];
    int qrow0 = q0 + w * 16 + g;
    int qrow1 = qrow0 + 8;
    bool qv0 = qrow0 < NTOK, qv1 = qrow1 < NTOK;
    const __half* qp0 = Qb + (size_t)qrow0 * HIDDEN;
    const __half* qp1 = Qb + (size_t)qrow1 * HIDDEN;
#pragma unroll
    for (int ks = 0; ks < 4; ks++) {
        int d0 = ks * 16 + 2 * tq;
        qa[ks][0] = qv0 ? *(const uint32_t*)&qp0[d0] : 0u;
        qa[ks][1] = qv1 ? *(const uint32_t*)&qp1[d0] : 0u;
        qa[ks][2] = qv0 ? *(const uint32_t*)&qp0[d0 + 8] : 0u;
        qa[ks][3] = qv1 ? *(const uint32_t*)&qp1[d0 + 8] : 0u;
    }

    float oacc[8][4];
#pragma unroll
    for (int i = 0; i < 8; i++)
#pragma unroll
        for (int j = 0; j < 4; j++) oacc[i][j] = 0.f;
    float m0 = -1e30f, m1 = -1e30f, l0 = 0.f, l1 = 0.f;

    uint32_t* pw = Ps + w * 16 * PST2;

    int vrow = (lane & 7) + ((lane >> 3) & 1) * 8;
    int vcol = (lane >> 4) * 8;
    uint32_t vs_base;
    asm("{ .reg .u64 t; cvta.to.shared.u64 t, %1; cvt.u32.u64 %0, t; }"
        : "=r"(vs_base) : "l"(Vs));
    uint32_t vaddr_t = vs_base + (uint32_t)(vrow * VST2 * 4 + vcol * 2);

    for (int kt = 0; kt < 25; kt++) {
        int k0 = kt * 64;
        __syncthreads();
#pragma unroll
        for (int i = 0; i < 4; i++) {
            int e = tid + i * 128;
            int r = e >> 3, c = e & 7;
            int ki = k0 + r;
            uint4 kv, vv;
            if (ki < NTOK) {
                kv = *(const uint4*)&Kb[(size_t)ki * HIDDEN + c * 8];
                vv = *(const uint4*)&Vb[(size_t)ki * HIDDEN + c * 8];
            } else {
                kv = make_uint4(0u, 0u, 0u, 0u);
                vv = kv;
            }
            *(uint4*)&Ks[r * KST2 + c * 4] = kv;
            *(uint4*)&Vs[r * VST2 + c * 4] = vv;
        }
        __syncthreads();

        float sacc[8][4];
#pragma unroll
        for (int nf = 0; nf < 8; nf++) {
            sacc[nf][0] = 0.f; sacc[nf][1] = 0.f; sacc[nf][2] = 0.f; sacc[nf][3] = 0.f;
            const uint32_t* krow = &Ks[(nf * 8 + g) * KST2];
#pragma unroll
            for (int ks = 0; ks < 4; ks++) {
                uint32_t b0 = krow[ks * 8 + tq];
                uint32_t b1 = krow[ks * 8 + tq + 4];
                mma16(sacc[nf], qa[ks][0], qa[ks][1], qa[ks][2], qa[ks][3], b0, b1);
            }
        }

        float mx0 = -1e30f, mx1 = -1e30f;
#pragma unroll
        for (int nf = 0; nf < 8; nf++) {
            int col0 = k0 + nf * 8 + 2 * tq;
            if (col0 >= NTOK)     { sacc[nf][0] = -1e30f; sacc[nf][2] = -1e30f; }
            if (col0 + 1 >= NTOK) { sacc[nf][1] = -1e30f; sacc[nf][3] = -1e30f; }
            mx0 = fmaxf(mx0, fmaxf(sacc[nf][0], sacc[nf][1]));
            mx1 = fmaxf(mx1, fmaxf(sacc[nf][2], sacc[nf][3]));
        }
        mx0 = fmaxf(mx0, __shfl_xor_sync(~0u, mx0, 1));
        mx0 = fmaxf(mx0, __shfl_xor_sync(~0u, mx0, 2));
        mx1 = fmaxf(mx1, __shfl_xor_sync(~0u, mx1, 1));
        mx1 = fmaxf(mx1, __shfl_xor_sync(~0u, mx1, 2));
        float mn0 = fmaxf(m0, mx0), mn1 = fmaxf(m1, mx1);
        float corr0 = __expf(m0 - mn0), corr1 = __expf(m1 - mn1);
        m0 = mn0; m1 = mn1;

        float ls0 = 0.f, ls1 = 0.f;
#pragma unroll
        for (int nf = 0; nf < 8; nf++) {
            float p0 = __expf(sacc[nf][0] - mn0);
            float p1 = __expf(sacc[nf][1] - mn0);
            float p2 = __expf(sacc[nf][2] - mn1);
            float p3 = __expf(sacc[nf][3] - mn1);
            ls0 += p0 + p1; ls1 += p2 + p3;
            pw[g * PST2 + nf * 4 + tq]       = pack2(p0, p1);
            pw[(g + 8) * PST2 + nf * 4 + tq] = pack2(p2, p3);
        }
        ls0 += __shfl_xor_sync(~0u, ls0, 1);
        ls0 += __shfl_xor_sync(~0u, ls0, 2);
        ls1 += __shfl_xor_sync(~0u, ls1, 1);
        ls1 += __shfl_xor_sync(~0u, ls1, 2);
        l0 = l0 * corr0 + ls0;
        l1 = l1 * corr1 + ls1;
#pragma unroll
        for (int nf2 = 0; nf2 < 8; nf2++) {
            oacc[nf2][0] *= corr0; oacc[nf2][1] *= corr0;
            oacc[nf2][2] *= corr1; oacc[nf2][3] *= corr1;
        }
        __syncwarp();

#pragma unroll
        for (int ks = 0; ks < 4; ks++) {
            uint32_t a0 = pw[g * PST2 + ks * 8 + tq];
            uint32_t a1 = pw[(g + 8) * PST2 + ks * 8 + tq];
            uint32_t a2 = pw[g * PST2 + ks * 8 + tq + 4];
            uint32_t a3 = pw[(g + 8) * PST2 + ks * 8 + tq + 4];
#pragma unroll
            for (int nfp = 0; nfp < 4; nfp++) {
                uint32_t addr = vaddr_t + (uint32_t)(ks * 16 * VST2 * 4 + nfp * 32);
                uint32_t v0, v1, v2, v3;
                asm volatile(
                    "ldmatrix.sync.aligned.m8n8.x4.trans.shared.b16 {%0,%1,%2,%3}, [%4];"
                    : "=r"(v0), "=r"(v1), "=r"(v2), "=r"(v3) : "r"(addr));
                mma16(oacc[nfp * 2],     a0, a1, a2, a3, v0, v1);
                mma16(oacc[nfp * 2 + 1], a0, a1, a2, a3, v2, v3);
            }
        }
        __syncwarp();
    }

    float inv0 = 1.f / l0, inv1 = 1.f / l1;
    __half* Ob = O + (size_t)b * NTOK * HIDDEN + h * HEADD;
#pragma unroll
    for (int nf2 = 0; nf2 < 8; nf2++) {
        int d0 = nf2 * 8 + 2 * tq;
        if (qv0)
            *(uint32_t*)&Ob[(size_t)qrow0 * HIDDEN + d0] =
                pack2(oacc[nf2][0] * inv0, oacc[nf2][1] * inv0);
        if (qv1)
            *(uint32_t*)&Ob[(size_t)qrow1 * HIDDEN + d0] =
                pack2(oacc[nf2][2] * inv1, oacc[nf2][3] * inv1);
    }
}

// ---------------- host orchestration ----------------
extern "C" void kernel_launch(void* const* d_in, const int* in_sizes, int n_in,
                              void* d_out, int out_size) {
    (void)in_sizes; (void)n_in; (void)out_size;
    const float* px      = (const float*)d_in[0];
    const float* patch_w = (const float*)d_in[1];
    const float* patch_b = (const float*)d_in[2];
    const float* ln1g = (const float*)d_in[3];
    const float* ln1b = (const float*)d_in[4];
    const float* qw = (const float*)d_in[5];
    const float* qb = (const float*)d_in[6];
    const float* kw = (const float*)d_in[7];
    const float* kb = (const float*)d_in[8];
    const float* vw = (const float*)d_in[9];
    const float* vb = (const float*)d_in[10];
    const float* pw = (const float*)d_in[11];
    const float* pb = (const float*)d_in[12];
    const float* ln2g = (const float*)d_in[13];
    const float* ln2b = (const float*)d_in[14];
    const float* fc1w = (const float*)d_in[15];
    const float* fc1b = (const float*)d_in[16];
    const float* fc2w = (const float*)d_in[17];
    const float* fc2b = (const float*)d_in[18];
    const float* lnfg = (const float*)d_in[19];
    const float* lnfb = (const float*)d_in[20];
    float* out = (float*)d_out;

    void *ph, *pq, *pk, *pqh, *pkh, *pvh, *pxnh, *paoh, *pmlph, *pcolh, *pwrh;
    cudaGetSymbolAddress(&ph,  g_h);
    cudaGetSymbolAddress(&pq,  g_q);
    cudaGetSymbolAddress(&pk,  g_k);
    cudaGetSymbolAddress(&pqh, g_qh);
    cudaGetSymbolAddress(&pkh, g_kh);
    cudaGetSymbolAddress(&pvh, g_vh);
    cudaGetSymbolAddress(&pxnh, g_xnh);
    cudaGetSymbolAddress(&paoh, g_aoh);
    cudaGetSymbolAddress(&pmlph, g_mlph);
    cudaGetSymbolAddress(&pcolh, g_colh);
    cudaGetSymbolAddress(&pwrh, g_wrh);
    float*  h    = (float*)ph;
    float*  q    = (float*)pq;
    float*  k    = (float*)pk;
    __half* qh   = (__half*)pqh;
    __half* kh   = (__half*)pkh;
    __half* vh   = (__half*)pvh;
    __half* xnh  = (__half*)pxnh;
    __half* aoh  = (__half*)paoh;
    __half* mlph = (__half*)pmlph;
    __half* colh = (__half*)pcolh;
    __half* wrh  = (__half*)pwrh;

    cudaFuncSetAttribute(tgemm<0>, cudaFuncAttributeMaxDynamicSharedMemorySize, GEMM_SMEM);
    cudaFuncSetAttribute(tgemm<1>, cudaFuncAttributeMaxDynamicSharedMemorySize, GEMM_SMEM);
    cudaFuncSetAttribute(tgemm<2>, cudaFuncAttributeMaxDynamicSharedMemorySize, GEMM_SMEM);
    cudaFuncSetAttribute(tgemm<3>, cudaFuncAttributeMaxDynamicSharedMemorySize, GEMM_SMEM);

    // patch embed
    im2col_k<<<(ROWS * PATCH_K + 255) / 256, 256>>>(px, colh);
    round4_k<<<(HIDDEN * PATCH_K / 4 + 255) / 256, 256>>>(patch_w, wrh, HIDDEN * PATCH_K / 4);
    tgemm<0><<<dim3(HIDDEN / 128, 25), 128, GEMM_SMEM>>>(
        colh, wrh, wrh, wrh, patch_b, patch_b, patch_b,
        nullptr, h, h, h, ROWS, HIDDEN, PATCH_K);

    for (int l = 0; l < LAYERS; l++) {
        size_t wo = (size_t)l * HIDDEN * HIDDEN;
        size_t bo = (size_t)l * HIDDEN;
        round_layer_k<<<(3 * MEG + 255) / 256, 256>>>(
            qw + wo, kw + wo, vw + wo, pw + wo,
            fc1w + (size_t)l * MLPD * HIDDEN, fc2w + (size_t)l * HIDDEN * MLPD, wrh);
        // attention block
        ln_k<true><<<ROWS, 256>>>(h, ln1g + bo, ln1b + bo, xnh);
        tgemm<3><<<dim3(24, 25), 128, GEMM_SMEM>>>(
            xnh, wrh, wrh + MEG, wrh + 2 * MEG, qb + bo, kb + bo, vb + bo,
            nullptr, q, k, (float*)vh, ROWS, HIDDEN, HIDDEN);
        rope_h<<<(ROWS * HEADS * 32 + 255) / 256, 256>>>(q, k, qh, kh);
        attn_h<<<dim3(25, BATCH * HEADS), 128>>>(qh, kh, vh, aoh);
        tgemm<2><<<dim3(8, 25), 128, GEMM_SMEM>>>(
            aoh, wrh + 3 * MEG, wrh, wrh, pb + bo, pb + bo, pb + bo,
            h, h, h, h, ROWS, HIDDEN, HIDDEN);
        // MLP block
        ln_k<true><<<ROWS, 256>>>(h, ln2g + bo, ln2b + bo, xnh);
        tgemm<1><<<dim3(MLPD / 128, 25), 128, GEMM_SMEM>>>(
            xnh, wrh + 4 * MEG, wrh, wrh, fc1b + (size_t)l * MLPD, fc1b, fc1b,
            nullptr, (float*)mlph, (float*)mlph, (float*)mlph, ROWS, MLPD, HIDDEN);
        tgemm<2><<<dim3(8, 25), 128, GEMM_SMEM>>>(
            mlph, wrh + 8 * MEG, wrh, wrh, fc2b + bo, fc2b, fc2b,
            h, h, h, h, ROWS, HIDDEN, MLPD);
    }

    ln_k<false><<<ROWS, 256>>>(h, lnfg, lnfb, out);
}

// round 10
// speedup vs baseline: 1.1100x; 1.1100x over previous
#include <cuda_runtime.h>
#include <cuda_fp16.h>
#include <math.h>
#include <stdint.h>

#define HIDDEN 1024
#define HEADS 16
#define HEADD 64
#define LAYERS 4
#define MLPD 4096
#define NTOK 1568
#define BATCH 2
#define ROWS (BATCH * NTOK)          // 3136
#define PATCH_K 1536                 // 3*2*16*16
#define MEG (1 << 20)

// ---------------- scratch (device globals; no allocation allowed) ----------------
__device__ float  g_h  [ROWS * HIDDEN];
__device__ float  g_q  [ROWS * HIDDEN];
__device__ float  g_k  [ROWS * HIDDEN];
__device__ __half g_qh  [ROWS * HIDDEN];
__device__ __half g_kh  [ROWS * HIDDEN];
__device__ __half g_vh  [ROWS * HIDDEN];
__device__ __half g_xnh [ROWS * HIDDEN];
__device__ __half g_aoh [ROWS * HIDDEN];
__device__ __half g_mlph[ROWS * MLPD];
__device__ __half g_colh[ROWS * PATCH_K];
__device__ __half g_wrh [12 * MEG];   // per-layer fp16 weights (or patch embed)

__device__ __forceinline__ uint32_t pack2(float a, float b) {
    __half2 h = __floats2half2_rn(a, b);
    return *(uint32_t*)&h;
}

// ---------------- weight conversion to fp16 ----------------
__global__ void round4_k(const float* __restrict__ in, __half* __restrict__ out, int n4) {
    int i = blockIdx.x * 256 + threadIdx.x;
    if (i >= n4) return;
    float4 v = ((const float4*)in)[i];
    ((uint2*)out)[i] = make_uint2(pack2(v.x, v.y), pack2(v.z, v.w));
}

__global__ void round_layer_k(const float* __restrict__ qw, const float* __restrict__ kw,
                              const float* __restrict__ vw, const float* __restrict__ pw,
                              const float* __restrict__ f1, const float* __restrict__ f2,
                              __half* __restrict__ out) {
    int i = blockIdx.x * 256 + threadIdx.x;      // float4 index, total 3*2^20
    if (i >= 3 * MEG) return;
    int u = i >> 18;
    const float* src;
    int base;
    if (u < 4) {
        src = (u == 0) ? qw : (u == 1) ? kw : (u == 2) ? vw : pw;
        base = i & 262143;
    } else if (u < 8) { src = f1; base = i - 4 * 262144; }
    else             { src = f2; base = i - 8 * 262144; }
    float4 v = ((const float4*)src)[base];
    ((uint2*)out)[i] = make_uint2(pack2(v.x, v.y), pack2(v.z, v.w));
}

// ---------------- im2col (stores fp16) ----------------
__global__ void im2col_k(const float* __restrict__ px, __half* __restrict__ col) {
    int idx = blockIdx.x * 256 + threadIdx.x;
    if (idx >= ROWS * PATCH_K) return;
    int m = idx / PATCH_K;
    int j = idx - m * PATCH_K;
    int c  = j >> 9;
    int r  = j & 511;
    int t  = r >> 8;
    int ph = (r >> 4) & 15;
    int pw = r & 15;
    int b = m / NTOK;
    int n = m - b * NTOK;
    int d  = n / 196;
    int rr = n - d * 196;
    int hy = rr / 14;
    int wx = rr - hy * 14;
    size_t src = ((size_t)((b * 16 + d * 2 + t) * 3 + c)) * (224 * 224)
               + (size_t)(hy * 16 + ph) * 224 + (wx * 16 + pw);
    col[idx] = __float2half_rn(px[src]);
}

// ---------------- fp16 tensor-core GEMM: cp.async 3-stage + ldmatrix ----------------
// CTA 128x128, 8 warps (2x4 warp grid, warp tile 64x32), 256 threads.
// smem layout per stage: A[128 rows][36 u32] then B[128 rows][36 u32] (row = 64 halves + pad)
__device__ __forceinline__ void mma16(float* c, uint32_t a0, uint32_t a1, uint32_t a2,
                                      uint32_t a3, uint32_t b0, uint32_t b1) {
    asm volatile(
        "mma.sync.aligned.m16n8k16.row.col.f32.f16.f16.f32 "
        "{%0,%1,%2,%3},{%4,%5,%6,%7},{%8,%9},{%0,%1,%2,%3};"
        : "+f"(c[0]), "+f"(c[1]), "+f"(c[2]), "+f"(c[3])
        : "r"(a0), "r"(a1), "r"(a2), "r"(a3), "r"(b0), "r"(b1));
}
__device__ __forceinline__ void cpa16(uint32_t dst, const void* src, int szbytes) {
    asm volatile("cp.async.cg.shared.global [%0], [%1], 16, %2;"
                 :: "r"(dst), "l"(src), "r"(szbytes) : "memory");
}
#define CP_COMMIT() asm volatile("cp.async.commit_group;" ::: "memory")

#define RSU 36                         // u32 row stride
#define TILE_U32 (128 * RSU)           // 4608 u32 per operand tile
#define STAGE_BYTES (2 * TILE_U32 * 4) // 36864
#define GEMM_SMEM (3 * STAGE_BYTES)    // 110592

template <int MODE>
__global__ __launch_bounds__(256, 2) void tgemm(
    const __half* __restrict__ A,
    const __half* __restrict__ B0, const __half* __restrict__ B1, const __half* __restrict__ B2,
    const float* __restrict__ bias0, const float* __restrict__ bias1, const float* __restrict__ bias2,
    const float* __restrict__ res, float* __restrict__ C0, float* __restrict__ C1,
    float* __restrict__ C2, int M, int N, int K)
{
    extern __shared__ uint32_t smu[];
    uint32_t smbase;
    asm("{ .reg .u64 t; cvta.to.shared.u64 t, %1; cvt.u32.u64 %0, t; }"
        : "=r"(smbase) : "l"(smu));

    int m0 = blockIdx.y * 128;
    int n0 = blockIdx.x * 128;
    const __half* B = B0;
    const float* bias = bias0;
    float* C = C0;
    int wsel = 0;
    if (MODE == 3) {
        wsel = n0 >> 10;
        if (wsel == 1) { B = B1; bias = bias1; C = C1; }
        else if (wsel == 2) { B = B2; bias = bias2; C = C2; }
        n0 &= 1023;
    }

    const int t = threadIdx.x;
    const int warp = t >> 5, lane = t & 31;
    const int wm = (warp >> 2) * 64, wn = (warp & 3) * 32;
    const int g = lane >> 2, tig = lane & 3;

    // ldmatrix per-lane source offsets (bytes within operand tile)
    const int asub = lane >> 3;                       // 0..3
    const uint32_t a_off =
        (uint32_t)((wm + ((asub & 1) << 3) + (lane & 7)) * (RSU * 4) + (asub >> 1) * 16);
    const int bcol = wn + (lane & 7) + ((lane >> 4) << 3);
    const uint32_t b_off =
        (uint32_t)(bcol * (RSU * 4) + ((lane >> 3) & 1) * 16);

    float acc[4][4][4];
#pragma unroll
    for (int i = 0; i < 4; i++)
#pragma unroll
        for (int j = 0; j < 4; j++)
#pragma unroll
            for (int q = 0; q < 4; q++) acc[i][j][q] = 0.f;

    const int NC = K >> 6;           // 64 halves per chunk

    auto stage_cp = [&](int s, int k0) {
        uint32_t sb = smbase + (uint32_t)s * STAGE_BYTES;
#pragma unroll
        for (int i = 0; i < 4; i++) {
            int e = t + i * 256;                    // 0..1023
            int row = e >> 3, c = e & 7;
            uint32_t off = (uint32_t)((row * RSU + c * 4) * 4);
            int gm = m0 + row;
            const __half* srcA = A + (size_t)(gm < M ? gm : 0) * K + k0 + c * 8;
            cpa16(sb + off, srcA, gm < M ? 16 : 0);
            int gn = n0 + row;
            const __half* srcB = B + (size_t)gn * K + k0 + c * 8;
            cpa16(sb + TILE_U32 * 4 + off, srcB, 16);
        }
    };

    auto compute = [&](int s) {
        uint32_t ab = smbase + (uint32_t)s * STAGE_BYTES;
        uint32_t bb = ab + TILE_U32 * 4;
#pragma unroll
        for (int gg = 0; gg < 4; gg++) {
            uint32_t pa[4][4];
#pragma unroll
            for (int fm = 0; fm < 4; fm++) {
                uint32_t addr = ab + a_off + (uint32_t)(fm * 16 * RSU * 4 + gg * 32);
                asm volatile(
                    "ldmatrix.sync.aligned.m8n8.x4.shared.b16 {%0,%1,%2,%3}, [%4];"
                    : "=r"(pa[fm][0]), "=r"(pa[fm][1]), "=r"(pa[fm][2]), "=r"(pa[fm][3])
                    : "r"(addr));
            }
            uint32_t pb[2][4];
#pragma unroll
            for (int p = 0; p < 2; p++) {
                uint32_t addr = bb + b_off + (uint32_t)(p * 16 * RSU * 4 + gg * 32);
                asm volatile(
                    "ldmatrix.sync.aligned.m8n8.x4.shared.b16 {%0,%1,%2,%3}, [%4];"
                    : "=r"(pb[p][0]), "=r"(pb[p][1]), "=r"(pb[p][2]), "=r"(pb[p][3])
                    : "r"(addr));
            }
#pragma unroll
            for (int fm = 0; fm < 4; fm++)
#pragma unroll
                for (int fn = 0; fn < 4; fn++)
                    mma16(acc[fm][fn], pa[fm][0], pa[fm][1], pa[fm][2], pa[fm][3],
                          pb[fn >> 1][(fn & 1) * 2], pb[fn >> 1][(fn & 1) * 2 + 1]);
        }
    };

    // prologue: stages 0,1
    stage_cp(0, 0);
    CP_COMMIT();
    if (NC > 1) stage_cp(1, 64);
    CP_COMMIT();

    for (int c = 0; c < NC; c++) {
        if (c + 2 < NC) { stage_cp((c + 2) % 3, (c + 2) << 6); CP_COMMIT(); }
        int rem = NC - 1 - c;
        if (rem >= 2)      asm volatile("cp.async.wait_group 2;" ::: "memory");
        else if (rem == 1) asm volatile("cp.async.wait_group 1;" ::: "memory");
        else               asm volatile("cp.async.wait_group 0;" ::: "memory");
        __syncthreads();
        compute(c % 3);
        __syncthreads();
    }

    // epilogue
    __half* Ch = (__half*)C;
    bool hstore = (MODE == 1) || (MODE == 3 && wsel == 2);
#pragma unroll
    for (int fm = 0; fm < 4; fm++) {
        int r0 = m0 + wm + fm * 16 + g;
#pragma unroll
        for (int fn = 0; fn < 4; fn++) {
            int col = n0 + wn + fn * 8 + 2 * tig;
            float b0v = bias[col], b1v = bias[col + 1];
#pragma unroll
            for (int hrow = 0; hrow < 2; hrow++) {
                int r = r0 + hrow * 8;
                if (r >= M) continue;
                float v0 = acc[fm][fn][hrow * 2 + 0] + b0v;
                float v1 = acc[fm][fn][hrow * 2 + 1] + b1v;
                if (MODE == 1) {
                    v0 = 0.5f * v0 * (1.f + erff(v0 * 0.70710678118654752f));
                    v1 = 0.5f * v1 * (1.f + erff(v1 * 0.70710678118654752f));
                }
                if (hstore) {
                    *(uint32_t*)&Ch[(size_t)r * N + col] = pack2(v0, v1);
                } else {
                    if (MODE == 2) {
                        const float* rr = &res[(size_t)r * N + col];
                        v0 += rr[0]; v1 += rr[1];
                    }
                    *(float2*)&C[(size_t)r * N + col] = make_float2(v0, v1);
                }
            }
        }
    }
}

// ---------------- LayerNorm (HALF_OUT: write fp16 for GEMM input) ----------------
template <bool HALF_OUT>
__global__ __launch_bounds__(256) void ln_k(
    const float* __restrict__ x, const float* __restrict__ g,
    const float* __restrict__ b, void* __restrict__ yv)
{
    __shared__ float red[8];
    __shared__ float stat[2];
    int row = blockIdx.x, tid = threadIdx.x;
    const float* xr = x + (size_t)row * HIDDEN;
    float v[4];
    float s = 0.f;
#pragma unroll
    for (int i = 0; i < 4; i++) { v[i] = xr[tid + i * 256]; s += v[i]; }
#pragma unroll
    for (int o = 16; o > 0; o >>= 1) s += __shfl_xor_sync(~0u, s, o);
    if ((tid & 31) == 0) red[tid >> 5] = s;
    __syncthreads();
    if (tid < 32) {
        float t = (tid < 8) ? red[tid] : 0.f;
#pragma unroll
        for (int o = 4; o > 0; o >>= 1) t += __shfl_xor_sync(~0u, t, o);
        if (tid == 0) stat[0] = t * (1.f / HIDDEN);
    }
    __syncthreads();
    float mu = stat[0];
    float s2 = 0.f;
#pragma unroll
    for (int i = 0; i < 4; i++) { float d = v[i] - mu; s2 += d * d; }
#pragma unroll
    for (int o = 16; o > 0; o >>= 1) s2 += __shfl_xor_sync(~0u, s2, o);
    if ((tid & 31) == 0) red[tid >> 5] = s2;
    __syncthreads();
    if (tid < 32) {
        float t = (tid < 8) ? red[tid] : 0.f;
#pragma unroll
        for (int o = 4; o > 0; o >>= 1) t += __shfl_xor_sync(~0u, t, o);
        if (tid == 0) stat[1] = rsqrtf(t * (1.f / HIDDEN) + 1e-6f);
    }
    __syncthreads();
    float rs = stat[1];
#pragma unroll
    for (int i = 0; i < 4; i++) {
        int c = tid + i * 256;
        float o = (v[i] - mu) * rs * g[c] + b[c];
        if (HALF_OUT) ((__half*)yv)[(size_t)row * HIDDEN + c] = __float2half_rn(o);
        else          ((float*)yv)[(size_t)row * HIDDEN + c] = o;
    }
}

// ---------------- RoPE: fp32 q/k in -> fp16 q (pre-scaled 1/8) / k out ----------
__global__ void rope_h(const float* __restrict__ q, const float* __restrict__ k,
                       __half* __restrict__ qh, __half* __restrict__ kh) {
    int idx = blockIdx.x * 256 + threadIdx.x;
    const int TOTAL = ROWS * HEADS * 32;
    if (idx >= TOTAL) return;
    int j = idx & 31;                // pair index within head dim (2*j, 2*j+1)
    int t = idx >> 5;
    int h = t & 15;
    int bn = t >> 4;
    size_t base = (size_t)bn * HIDDEN + h * HEADD + 2 * j;
    float x0 = q[base], x1 = q[base + 1];
    float y0 = k[base], y1 = k[base + 1];
    if (j < 30) {
        int n = bn % NTOK;
        int a = j / 10, i = j - a * 10;
        int dpos = n / 196, r = n - dpos * 196;
        int pos = (a == 0) ? dpos : (a == 1) ? (r / 14) : (r % 14);
        int i0 = (2 * i) % 10, i1 = (2 * i + 1) % 10;
        const float LN1E4_O10 = 0.92103403719761840f;
        float f0 = (float)pos * expf(-LN1E4_O10 * (float)i0);
        float f1 = (float)pos * expf(-LN1E4_O10 * (float)i1);
        float s0, c0, s1, c1;
        sincosf(f0, &s0, &c0);
        sincosf(f1, &s1, &c1);
        float nq0 = x0 * c0 - x1 * s0;
        float nq1 = x1 * c1 + x0 * s1;
        float nk0 = y0 * c0 - y1 * s0;
        float nk1 = y1 * c1 + y0 * s1;
        x0 = nq0; x1 = nq1; y0 = nk0; y1 = nk1;
    }
    *(uint32_t*)&qh[base] = pack2(x0 * 0.125f, x1 * 0.125f);
    *(uint32_t*)&kh[base] = pack2(y0, y1);
}

// ---------------- Flash attention, fp16 m16n8k16 ----------------
#define KST2 36   // u32 row stride (72 halves); 36 % 32 == 4 -> conflict-free frags
#define VST2 36
#define PST2 36

__global__ __launch_bounds__(128) void attn_h(
    const __half* __restrict__ Q, const __half* __restrict__ K,
    const __half* __restrict__ V, __half* __restrict__ O)
{
    __shared__ uint32_t Ks[64 * KST2];
    __shared__ uint32_t Vs[64 * VST2];
    __shared__ uint32_t Ps[64 * PST2];

    int b = blockIdx.y >> 4, h = blockIdx.y & 15;
    int q0 = blockIdx.x * 64;
    int tid = threadIdx.x, w = tid >> 5, lane = tid & 31;
    int g = lane >> 2, tq = lane & 3;

    const __half* Qb = Q + (size_t)b * NTOK * HIDDEN + h * HEADD;
    const __half* Kb = K + (size_t)b * NTOK * HIDDEN + h * HEADD;
    const __half* Vb = V + (size_t)b * NTOK * HIDDEN + h * HEADD;

    uint32_t qa[4][4];
    int qrow0 = q0 + w * 16 + g;
    int qrow1 = qrow0 + 8;
    bool qv0 = qrow0 < NTOK, qv1 = qrow1 < NTOK;
    const __half* qp0 = Qb + (size_t)qrow0 * HIDDEN;
    const __half* qp1 = Qb + (size_t)qrow1 * HIDDEN;
#pragma unroll
    for (int ks = 0; ks < 4; ks++) {
        int d0 = ks * 16 + 2 * tq;
        qa[ks][0] = qv0 ? *(const uint32_t*)&qp0[d0] : 0u;
        qa[ks][1] = qv1 ? *(const uint32_t*)&qp1[d0] : 0u;
        qa[ks][2] = qv0 ? *(const uint32_t*)&qp0[d0 + 8] : 0u;
        qa[ks][3] = qv1 ? *(const uint32_t*)&qp1[d0 + 8] : 0u;
    }

    float oacc[8][4];
#pragma unroll
    for (int i = 0; i < 8; i++)
#pragma unroll
        for (int j = 0; j < 4; j++) oacc[i][j] = 0.f;
    float m0 = -1e30f, m1 = -1e30f, l0 = 0.f, l1 = 0.f;

    uint32_t* pw = Ps + w * 16 * PST2;

    int vrow = (lane & 7) + ((lane >> 3) & 1) * 8;
    int vcol = (lane >> 4) * 8;
    uint32_t vs_base;
    asm("{ .reg .u64 t; cvta.to.shared.u64 t, %1; cvt.u32.u64 %0, t; }"
        : "=r"(vs_base) : "l"(Vs));
    uint32_t vaddr_t = vs_base + (uint32_t)(vrow * VST2 * 4 + vcol * 2);

    for (int kt = 0; kt < 25; kt++) {
        int k0 = kt * 64;
        __syncthreads();
#pragma unroll
        for (int i = 0; i < 4; i++) {
            int e = tid + i * 128;
            int r = e >> 3, c = e & 7;
            int ki = k0 + r;
            uint4 kv, vv;
            if (ki < NTOK) {
                kv = *(const uint4*)&Kb[(size_t)ki * HIDDEN + c * 8];
                vv = *(const uint4*)&Vb[(size_t)ki * HIDDEN + c * 8];
            } else {
                kv = make_uint4(0u, 0u, 0u, 0u);
                vv = kv;
            }
            *(uint4*)&Ks[r * KST2 + c * 4] = kv;
            *(uint4*)&Vs[r * VST2 + c * 4] = vv;
        }
        __syncthreads();

        float sacc[8][4];
#pragma unroll
        for (int nf = 0; nf < 8; nf++) {
            sacc[nf][0] = 0.f; sacc[nf][1] = 0.f; sacc[nf][2] = 0.f; sacc[nf][3] = 0.f;
            const uint32_t* krow = &Ks[(nf * 8 + g) * KST2];
#pragma unroll
            for (int ks = 0; ks < 4; ks++) {
                uint32_t b0 = krow[ks * 8 + tq];
                uint32_t b1 = krow[ks * 8 + tq + 4];
                mma16(sacc[nf], qa[ks][0], qa[ks][1], qa[ks][2], qa[ks][3], b0, b1);
            }
        }

        float mx0 = -1e30f, mx1 = -1e30f;
#pragma unroll
        for (int nf = 0; nf < 8; nf++) {
            int col0 = k0 + nf * 8 + 2 * tq;
            if (col0 >= NTOK)     { sacc[nf][0] = -1e30f; sacc[nf][2] = -1e30f; }
            if (col0 + 1 >= NTOK) { sacc[nf][1] = -1e30f; sacc[nf][3] = -1e30f; }
            mx0 = fmaxf(mx0, fmaxf(sacc[nf][0], sacc[nf][1]));
            mx1 = fmaxf(mx1, fmaxf(sacc[nf][2], sacc[nf][3]));
        }
        mx0 = fmaxf(mx0, __shfl_xor_sync(~0u, mx0, 1));
        mx0 = fmaxf(mx0, __shfl_xor_sync(~0u, mx0, 2));
        mx1 = fmaxf(mx1, __shfl_xor_sync(~0u, mx1, 1));
        mx1 = fmaxf(mx1, __shfl_xor_sync(~0u, mx1, 2));
        float mn0 = fmaxf(m0, mx0), mn1 = fmaxf(m1, mx1);
        float corr0 = __expf(m0 - mn0), corr1 = __expf(m1 - mn1);
        m0 = mn0; m1 = mn1;

        float ls0 = 0.f, ls1 = 0.f;
#pragma unroll
        for (int nf = 0; nf < 8; nf++) {
            float p0 = __expf(sacc[nf][0] - mn0);
            float p1 = __expf(sacc[nf][1] - mn0);
            float p2 = __expf(sacc[nf][2] - mn1);
            float p3 = __expf(sacc[nf][3] - mn1);
            ls0 += p0 + p1; ls1 += p2 + p3;
            pw[g * PST2 + nf * 4 + tq]       = pack2(p0, p1);
            pw[(g + 8) * PST2 + nf * 4 + tq] = pack2(p2, p3);
        }
        ls0 += __shfl_xor_sync(~0u, ls0, 1);
        ls0 += __shfl_xor_sync(~0u, ls0, 2);
        ls1 += __shfl_xor_sync(~0u, ls1, 1);
        ls1 += __shfl_xor_sync(~0u, ls1, 2);
        l0 = l0 * corr0 + ls0;
        l1 = l1 * corr1 + ls1;
#pragma unroll
        for (int nf2 = 0; nf2 < 8; nf2++) {
            oacc[nf2][0] *= corr0; oacc[nf2][1] *= corr0;
            oacc[nf2][2] *= corr1; oacc[nf2][3] *= corr1;
        }
        __syncwarp();

#pragma unroll
        for (int ks = 0; ks < 4; ks++) {
            uint32_t a0 = pw[g * PST2 + ks * 8 + tq];
            uint32_t a1 = pw[(g + 8) * PST2 + ks * 8 + tq];
            uint32_t a2 = pw[g * PST2 + ks * 8 + tq + 4];
            uint32_t a3 = pw[(g + 8) * PST2 + ks * 8 + tq + 4];
#pragma unroll
            for (int nfp = 0; nfp < 4; nfp++) {
                uint32_t addr = vaddr_t + (uint32_t)(ks * 16 * VST2 * 4 + nfp * 32);
                uint32_t v0, v1, v2, v3;
                asm volatile(
                    "ldmatrix.sync.aligned.m8n8.x4.trans.shared.b16 {%0,%1,%2,%3}, [%4];"
                    : "=r"(v0), "=r"(v1), "=r"(v2), "=r"(v3) : "r"(addr));
                mma16(oacc[nfp * 2],     a0, a1, a2, a3, v0, v1);
                mma16(oacc[nfp * 2 + 1], a0, a1, a2, a3, v2, v3);
            }
        }
        __syncwarp();
    }

    float inv0 = 1.f / l0, inv1 = 1.f / l1;
    __half* Ob = O + (size_t)b * NTOK * HIDDEN + h * HEADD;
#pragma unroll
    for (int nf2 = 0; nf2 < 8; nf2++) {
        int d0 = nf2 * 8 + 2 * tq;
        if (qv0)
            *(uint32_t*)&Ob[(size_t)qrow0 * HIDDEN + d0] =
                pack2(oacc[nf2][0] * inv0, oacc[nf2][1] * inv0);
        if (qv1)
            *(uint32_t*)&Ob[(size_t)qrow1 * HIDDEN + d0] =
                pack2(oacc[nf2][2] * inv1, oacc[nf2][3] * inv1);
    }
}

// ---------------- host orchestration ----------------
extern "C" void kernel_launch(void* const* d_in, const int* in_sizes, int n_in,
                              void* d_out, int out_size) {
    (void)in_sizes; (void)n_in; (void)out_size;
    const float* px      = (const float*)d_in[0];
    const float* patch_w = (const float*)d_in[1];
    const float* patch_b = (const float*)d_in[2];
    const float* ln1g = (const float*)d_in[3];
    const float* ln1b = (const float*)d_in[4];
    const float* qw = (const float*)d_in[5];
    const float* qb = (const float*)d_in[6];
    const float* kw = (const float*)d_in[7];
    const float* kb = (const float*)d_in[8];
    const float* vw = (const float*)d_in[9];
    const float* vb = (const float*)d_in[10];
    const float* pw = (const float*)d_in[11];
    const float* pb = (const float*)d_in[12];
    const float* ln2g = (const float*)d_in[13];
    const float* ln2b = (const float*)d_in[14];
    const float* fc1w = (const float*)d_in[15];
    const float* fc1b = (const float*)d_in[16];
    const float* fc2w = (const float*)d_in[17];
    const float* fc2b = (const float*)d_in[18];
    const float* lnfg = (const float*)d_in[19];
    const float* lnfb = (const float*)d_in[20];
    float* out = (float*)d_out;

    void *ph, *pq, *pk, *pqh, *pkh, *pvh, *pxnh, *paoh, *pmlph, *pcolh, *pwrh;
    cudaGetSymbolAddress(&ph,  g_h);
    cudaGetSymbolAddress(&pq,  g_q);
    cudaGetSymbolAddress(&pk,  g_k);
    cudaGetSymbolAddress(&pqh, g_qh);
    cudaGetSymbolAddress(&pkh, g_kh);
    cudaGetSymbolAddress(&pvh, g_vh);
    cudaGetSymbolAddress(&pxnh, g_xnh);
    cudaGetSymbolAddress(&paoh, g_aoh);
    cudaGetSymbolAddress(&pmlph, g_mlph);
    cudaGetSymbolAddress(&pcolh, g_colh);
    cudaGetSymbolAddress(&pwrh, g_wrh);
    float*  h    = (float*)ph;
    float*  q    = (float*)pq;
    float*  k    = (float*)pk;
    __half* qh   = (__half*)pqh;
    __half* kh   = (__half*)pkh;
    __half* vh   = (__half*)pvh;
    __half* xnh  = (__half*)pxnh;
    __half* aoh  = (__half*)paoh;
    __half* mlph = (__half*)pmlph;
    __half* colh = (__half*)pcolh;
    __half* wrh  = (__half*)pwrh;

    cudaFuncSetAttribute(tgemm<0>, cudaFuncAttributeMaxDynamicSharedMemorySize, GEMM_SMEM);
    cudaFuncSetAttribute(tgemm<1>, cudaFuncAttributeMaxDynamicSharedMemorySize, GEMM_SMEM);
    cudaFuncSetAttribute(tgemm<2>, cudaFuncAttributeMaxDynamicSharedMemorySize, GEMM_SMEM);
    cudaFuncSetAttribute(tgemm<3>, cudaFuncAttributeMaxDynamicSharedMemorySize, GEMM_SMEM);

    // patch embed
    im2col_k<<<(ROWS * PATCH_K + 255) / 256, 256>>>(px, colh);
    round4_k<<<(HIDDEN * PATCH_K / 4 + 255) / 256, 256>>>(patch_w, wrh, HIDDEN * PATCH_K / 4);
    tgemm<0><<<dim3(HIDDEN / 128, 25), 256, GEMM_SMEM>>>(
        colh, wrh, wrh, wrh, patch_b, patch_b, patch_b,
        nullptr, h, h, h, ROWS, HIDDEN, PATCH_K);

    for (int l = 0; l < LAYERS; l++) {
        size_t wo = (size_t)l * HIDDEN * HIDDEN;
        size_t bo = (size_t)l * HIDDEN;
        round_layer_k<<<(3 * MEG + 255) / 256, 256>>>(
            qw + wo, kw + wo, vw + wo, pw + wo,
            fc1w + (size_t)l * MLPD * HIDDEN, fc2w + (size_t)l * HIDDEN * MLPD, wrh);
        // attention block
        ln_k<true><<<ROWS, 256>>>(h, ln1g + bo, ln1b + bo, xnh);
        tgemm<3><<<dim3(24, 25), 256, GEMM_SMEM>>>(
            xnh, wrh, wrh + MEG, wrh + 2 * MEG, qb + bo, kb + bo, vb + bo,
            nullptr, q, k, (float*)vh, ROWS, HIDDEN, HIDDEN);
        rope_h<<<(ROWS * HEADS * 32 + 255) / 256, 256>>>(q, k, qh, kh);
        attn_h<<<dim3(25, BATCH * HEADS), 128>>>(qh, kh, vh, aoh);
        tgemm<2><<<dim3(8, 25), 256, GEMM_SMEM>>>(
            aoh, wrh + 3 * MEG, wrh, wrh, pb + bo, pb + bo, pb + bo,
            h, h, h, h, ROWS, HIDDEN, HIDDEN);
        // MLP block
        ln_k<true><<<ROWS, 256>>>(h, ln2g + bo, ln2b + bo, xnh);
        tgemm<1><<<dim3(MLPD / 128, 25), 256, GEMM_SMEM>>>(
            xnh, wrh + 4 * MEG, wrh, wrh, fc1b + (size_t)l * MLPD, fc1b, fc1b,
            nullptr, (float*)mlph, (float*)mlph, (float*)mlph, ROWS, MLPD, HIDDEN);
        tgemm<2><<<dim3(8, 25), 256, GEMM_SMEM>>>(
            mlph, wrh + 8 * MEG, wrh, wrh, fc2b + bo, fc2b, fc2b,
            h, h, h, h, ROWS, HIDDEN, MLPD);
    }

    ln_k<false><<<ROWS, 256>>>(h, lnfg, lnfb, out);
}

// round 11
// speedup vs baseline: 1.1216x; 1.0105x over previous
#include <cuda_runtime.h>
#include <cuda_fp16.h>
#include <math.h>
#include <stdint.h>

#define HIDDEN 1024
#define HEADS 16
#define HEADD 64
#define LAYERS 4
#define MLPD 4096
#define NTOK 1568
#define BATCH 2
#define ROWS (BATCH * NTOK)          // 3136
#define PATCH_K 1536                 // 3*2*16*16
#define MEG (1 << 20)

// ---------------- scratch (device globals; no allocation allowed) ----------------
__device__ float  g_h  [ROWS * HIDDEN];
__device__ __half g_qh  [ROWS * HIDDEN];
__device__ __half g_kh  [ROWS * HIDDEN];
__device__ __half g_vh  [ROWS * HIDDEN];
__device__ __half g_xnh [ROWS * HIDDEN];
__device__ __half g_aoh [ROWS * HIDDEN];
__device__ __half g_mlph[ROWS * MLPD];
__device__ __half g_colh[ROWS * PATCH_K];
__device__ __half g_wrh [12 * MEG];   // per-layer fp16 weights (or patch embed)

// omega_i = 10000^(-i/10), i = 0..9
__constant__ float c_OM[10] = {
    1.0f, 0.3981071705534972f, 0.15848931924611134f, 0.06309573444801933f,
    0.025118864315095794f, 0.01f, 0.003981071705534973f, 0.001584893192461113f,
    0.0006309573444801932f, 0.00025118864315095795f
};

__device__ __forceinline__ uint32_t pack2(float a, float b) {
    __half2 h = __floats2half2_rn(a, b);
    return *(uint32_t*)&h;
}

// ---------------- weight conversion to fp16 ----------------
__global__ void round4_k(const float* __restrict__ in, __half* __restrict__ out, int n4) {
    int i = blockIdx.x * 256 + threadIdx.x;
    if (i >= n4) return;
    float4 v = ((const float4*)in)[i];
    ((uint2*)out)[i] = make_uint2(pack2(v.x, v.y), pack2(v.z, v.w));
}

__global__ void round_layer_k(const float* __restrict__ qw, const float* __restrict__ kw,
                              const float* __restrict__ vw, const float* __restrict__ pw,
                              const float* __restrict__ f1, const float* __restrict__ f2,
                              __half* __restrict__ out) {
    int i = blockIdx.x * 256 + threadIdx.x;      // float4 index, total 3*2^20
    if (i >= 3 * MEG) return;
    int u = i >> 18;
    const float* src;
    int base;
    if (u < 4) {
        src = (u == 0) ? qw : (u == 1) ? kw : (u == 2) ? vw : pw;
        base = i & 262143;
    } else if (u < 8) { src = f1; base = i - 4 * 262144; }
    else             { src = f2; base = i - 8 * 262144; }
    float4 v = ((const float4*)src)[base];
    ((uint2*)out)[i] = make_uint2(pack2(v.x, v.y), pack2(v.z, v.w));
}

// ---------------- im2col (stores fp16) ----------------
__global__ void im2col_k(const float* __restrict__ px, __half* __restrict__ col) {
    int idx = blockIdx.x * 256 + threadIdx.x;
    if (idx >= ROWS * PATCH_K) return;
    int m = idx / PATCH_K;
    int j = idx - m * PATCH_K;
    int c  = j >> 9;
    int r  = j & 511;
    int t  = r >> 8;
    int ph = (r >> 4) & 15;
    int pw = r & 15;
    int b = m / NTOK;
    int n = m - b * NTOK;
    int d  = n / 196;
    int rr = n - d * 196;
    int hy = rr / 14;
    int wx = rr - hy * 14;
    size_t src = ((size_t)((b * 16 + d * 2 + t) * 3 + c)) * (224 * 224)
               + (size_t)(hy * 16 + ph) * 224 + (wx * 16 + pw);
    col[idx] = __float2half_rn(px[src]);
}

// ---------------- fp16 tensor-core GEMM: cp.async 3-stage + ldmatrix ----------------
// CTA 128x128, 8 warps (2x4 warp grid, warp tile 64x32), 256 threads.
// MODE 0: bias (f32 out), 1: bias+gelu (half out), 2: bias+residual (f32 out),
// MODE 3: fused QKV with in-register RoPE (q scaled 1/8) -> half out.
__device__ __forceinline__ void mma16(float* c, uint32_t a0, uint32_t a1, uint32_t a2,
                                      uint32_t a3, uint32_t b0, uint32_t b1) {
    asm volatile(
        "mma.sync.aligned.m16n8k16.row.col.f32.f16.f16.f32 "
        "{%0,%1,%2,%3},{%4,%5,%6,%7},{%8,%9},{%0,%1,%2,%3};"
        : "+f"(c[0]), "+f"(c[1]), "+f"(c[2]), "+f"(c[3])
        : "r"(a0), "r"(a1), "r"(a2), "r"(a3), "r"(b0), "r"(b1));
}
__device__ __forceinline__ void cpa16(uint32_t dst, const void* src, int szbytes) {
    asm volatile("cp.async.cg.shared.global [%0], [%1], 16, %2;"
                 :: "r"(dst), "l"(src), "r"(szbytes) : "memory");
}
#define CP_COMMIT() asm volatile("cp.async.commit_group;" ::: "memory")

#define RSU 36                         // u32 row stride
#define TILE_U32 (128 * RSU)           // 4608 u32 per operand tile
#define STAGE_BYTES (2 * TILE_U32 * 4) // 36864
#define GEMM_SMEM (3 * STAGE_BYTES)    // 110592

template <int MODE>
__global__ __launch_bounds__(256, 2) void tgemm(
    const __half* __restrict__ A,
    const __half* __restrict__ B0, const __half* __restrict__ B1, const __half* __restrict__ B2,
    const float* __restrict__ bias0, const float* __restrict__ bias1, const float* __restrict__ bias2,
    const float* __restrict__ res, float* __restrict__ C0, float* __restrict__ C1,
    float* __restrict__ C2, int M, int N, int K)
{
    extern __shared__ uint32_t smu[];
    uint32_t smbase;
    asm("{ .reg .u64 t; cvta.to.shared.u64 t, %1; cvt.u32.u64 %0, t; }"
        : "=r"(smbase) : "l"(smu));

    int m0 = blockIdx.y * 128;
    int n0 = blockIdx.x * 128;
    const __half* B = B0;
    const float* bias = bias0;
    float* C = C0;
    int wsel = 0;
    if (MODE == 3) {
        wsel = n0 >> 10;
        if (wsel == 1) { B = B1; bias = bias1; C = C1; }
        else if (wsel == 2) { B = B2; bias = bias2; C = C2; }
        n0 &= 1023;
    }

    const int t = threadIdx.x;
    const int warp = t >> 5, lane = t & 31;
    const int wm = (warp >> 2) * 64, wn = (warp & 3) * 32;
    const int g = lane >> 2, tig = lane & 3;

    const int asub = lane >> 3;
    const uint32_t a_off =
        (uint32_t)((wm + ((asub & 1) << 3) + (lane & 7)) * (RSU * 4) + (asub >> 1) * 16);
    const int bcol = wn + (lane & 7) + ((lane >> 4) << 3);
    const uint32_t b_off =
        (uint32_t)(bcol * (RSU * 4) + ((lane >> 3) & 1) * 16);

    float acc[4][4][4];
#pragma unroll
    for (int i = 0; i < 4; i++)
#pragma unroll
        for (int j = 0; j < 4; j++)
#pragma unroll
            for (int q = 0; q < 4; q++) acc[i][j][q] = 0.f;

    const int NC = K >> 6;           // 64 halves per chunk

    auto stage_cp = [&](int s, int k0) {
        uint32_t sb = smbase + (uint32_t)s * STAGE_BYTES;
#pragma unroll
        for (int i = 0; i < 4; i++) {
            int e = t + i * 256;
            int row = e >> 3, c = e & 7;
            uint32_t off = (uint32_t)((row * RSU + c * 4) * 4);
            int gm = m0 + row;
            const __half* srcA = A + (size_t)(gm < M ? gm : 0) * K + k0 + c * 8;
            cpa16(sb + off, srcA, gm < M ? 16 : 0);
            int gn = n0 + row;
            const __half* srcB = B + (size_t)gn * K + k0 + c * 8;
            cpa16(sb + TILE_U32 * 4 + off, srcB, 16);
        }
    };

    auto compute = [&](int s) {
        uint32_t ab = smbase + (uint32_t)s * STAGE_BYTES;
        uint32_t bb = ab + TILE_U32 * 4;
#pragma unroll
        for (int gg = 0; gg < 4; gg++) {
            uint32_t pa[4][4];
#pragma unroll
            for (int fm = 0; fm < 4; fm++) {
                uint32_t addr = ab + a_off + (uint32_t)(fm * 16 * RSU * 4 + gg * 32);
                asm volatile(
                    "ldmatrix.sync.aligned.m8n8.x4.shared.b16 {%0,%1,%2,%3}, [%4];"
                    : "=r"(pa[fm][0]), "=r"(pa[fm][1]), "=r"(pa[fm][2]), "=r"(pa[fm][3])
                    : "r"(addr));
            }
            uint32_t pb[2][4];
#pragma unroll
            for (int p = 0; p < 2; p++) {
                uint32_t addr = bb + b_off + (uint32_t)(p * 16 * RSU * 4 + gg * 32);
                asm volatile(
                    "ldmatrix.sync.aligned.m8n8.x4.shared.b16 {%0,%1,%2,%3}, [%4];"
                    : "=r"(pb[p][0]), "=r"(pb[p][1]), "=r"(pb[p][2]), "=r"(pb[p][3])
                    : "r"(addr));
            }
#pragma unroll
            for (int fm = 0; fm < 4; fm++)
#pragma unroll
                for (int fn = 0; fn < 4; fn++)
                    mma16(acc[fm][fn], pa[fm][0], pa[fm][1], pa[fm][2], pa[fm][3],
                          pb[fn >> 1][(fn & 1) * 2], pb[fn >> 1][(fn & 1) * 2 + 1]);
        }
    };

    // prologue: stages 0,1
    stage_cp(0, 0);
    CP_COMMIT();
    if (NC > 1) { stage_cp(1, 64); CP_COMMIT(); }

    // single-sync mainloop
    for (int c = 0; c < NC; c++) {
        if (c + 1 < NC) asm volatile("cp.async.wait_group 1;" ::: "memory");
        else            asm volatile("cp.async.wait_group 0;" ::: "memory");
        __syncthreads();
        if (c + 2 < NC) { stage_cp((c + 2) % 3, (c + 2) << 6); CP_COMMIT(); }
        compute(c % 3);
    }

    // epilogue
    __half* Ch = (__half*)C;
#pragma unroll
    for (int fm = 0; fm < 4; fm++) {
        int r0 = m0 + wm + fm * 16 + g;
#pragma unroll
        for (int fn = 0; fn < 4; fn++) {
            int col = n0 + wn + fn * 8 + 2 * tig;
            float b0v = bias[col], b1v = bias[col + 1];
            // RoPE pair parameters (MODE 3, q/k only)
            float om0 = 0.f, om1 = 0.f;
            int axis = 3;
            if (MODE == 3 && wsel < 2) {
                int j = (col & 63) >> 1;
                if (j < 30) {
                    axis = j / 10;
                    int i = j - axis * 10;
                    int i0 = (2 * i) % 10, i1 = (2 * i + 1) % 10;
                    om0 = c_OM[i0]; om1 = c_OM[i1];
                }
            }
#pragma unroll
            for (int hrow = 0; hrow < 2; hrow++) {
                int r = r0 + hrow * 8;
                if (r >= M) continue;
                float v0 = acc[fm][fn][hrow * 2 + 0] + b0v;
                float v1 = acc[fm][fn][hrow * 2 + 1] + b1v;
                if (MODE == 1) {
                    v0 = 0.5f * v0 * (1.f + erff(v0 * 0.70710678118654752f));
                    v1 = 0.5f * v1 * (1.f + erff(v1 * 0.70710678118654752f));
                    *(uint32_t*)&Ch[(size_t)r * N + col] = pack2(v0, v1);
                } else if (MODE == 3) {
                    if (wsel < 2 && axis < 3) {
                        int n = r % NTOK;
                        int dpos = n / 196, rem = n - dpos * 196;
                        int pos = (axis == 0) ? dpos : (axis == 1) ? (rem / 14) : (rem % 14);
                        float fp = (float)pos;
                        float s0, c0, s1, c1;
                        __sincosf(fp * om0, &s0, &c0);
                        __sincosf(fp * om1, &s1, &c1);
                        float nv0 = v0 * c0 - v1 * s0;
                        float nv1 = v1 * c1 + v0 * s1;
                        v0 = nv0; v1 = nv1;
                    }
                    if (wsel == 0) { v0 *= 0.125f; v1 *= 0.125f; }
                    *(uint32_t*)&Ch[(size_t)r * N + col] = pack2(v0, v1);
                } else {
                    if (MODE == 2) {
                        const float* rr = &res[(size_t)r * N + col];
                        v0 += rr[0]; v1 += rr[1];
                    }
                    *(float2*)&C[(size_t)r * N + col] = make_float2(v0, v1);
                }
            }
        }
    }
}

// ---------------- LayerNorm (HALF_OUT: write fp16 for GEMM input) ----------------
template <bool HALF_OUT>
__global__ __launch_bounds__(256) void ln_k(
    const float* __restrict__ x, const float* __restrict__ g,
    const float* __restrict__ b, void* __restrict__ yv)
{
    __shared__ float red[8];
    __shared__ float stat[2];
    int row = blockIdx.x, tid = threadIdx.x;
    const float* xr = x + (size_t)row * HIDDEN;
    float v[4];
    float s = 0.f;
#pragma unroll
    for (int i = 0; i < 4; i++) { v[i] = xr[tid + i * 256]; s += v[i]; }
#pragma unroll
    for (int o = 16; o > 0; o >>= 1) s += __shfl_xor_sync(~0u, s, o);
    if ((tid & 31) == 0) red[tid >> 5] = s;
    __syncthreads();
    if (tid < 32) {
        float t = (tid < 8) ? red[tid] : 0.f;
#pragma unroll
        for (int o = 4; o > 0; o >>= 1) t += __shfl_xor_sync(~0u, t, o);
        if (tid == 0) stat[0] = t * (1.f / HIDDEN);
    }
    __syncthreads();
    float mu = stat[0];
    float s2 = 0.f;
#pragma unroll
    for (int i = 0; i < 4; i++) { float d = v[i] - mu; s2 += d * d; }
#pragma unroll
    for (int o = 16; o > 0; o >>= 1) s2 += __shfl_xor_sync(~0u, s2, o);
    if ((tid & 31) == 0) red[tid >> 5] = s2;
    __syncthreads();
    if (tid < 32) {
        float t = (tid < 8) ? red[tid] : 0.f;
#pragma unroll
        for (int o = 4; o > 0; o >>= 1) t += __shfl_xor_sync(~0u, t, o);
        if (tid == 0) stat[1] = rsqrtf(t * (1.f / HIDDEN) + 1e-6f);
    }
    __syncthreads();
    float rs = stat[1];
#pragma unroll
    for (int i = 0; i < 4; i++) {
        int c = tid + i * 256;
        float o = (v[i] - mu) * rs * g[c] + b[c];
        if (HALF_OUT) ((__half*)yv)[(size_t)row * HIDDEN + c] = __float2half_rn(o);
        else          ((float*)yv)[(size_t)row * HIDDEN + c] = o;
    }
}

// ---------------- Flash attention, fp16 m16n8k16 ----------------
#define KST2 36   // u32 row stride (72 halves); 36 % 32 == 4 -> conflict-free frags
#define VST2 36
#define PST2 36

__global__ __launch_bounds__(128) void attn_h(
    const __half* __restrict__ Q, const __half* __restrict__ K,
    const __half* __restrict__ V, __half* __restrict__ O)
{
    __shared__ uint32_t Ks[64 * KST2];
    __shared__ uint32_t Vs[64 * VST2];
    __shared__ uint32_t Ps[64 * PST2];

    int b = blockIdx.y >> 4, h = blockIdx.y & 15;
    int q0 = blockIdx.x * 64;
    int tid = threadIdx.x, w = tid >> 5, lane = tid & 31;
    int g = lane >> 2, tq = lane & 3;

    const __half* Qb = Q + (size_t)b * NTOK * HIDDEN + h * HEADD;
    const __half* Kb = K + (size_t)b * NTOK * HIDDEN + h * HEADD;
    const __half* Vb = V + (size_t)b * NTOK * HIDDEN + h * HEADD;

    uint32_t qa[4][4];
    int qrow0 = q0 + w * 16 + g;
    int qrow1 = qrow0 + 8;
    bool qv0 = qrow0 < NTOK, qv1 = qrow1 < NTOK;
    const __half* qp0 = Qb + (size_t)qrow0 * HIDDEN;
    const __half* qp1 = Qb + (size_t)qrow1 * HIDDEN;
#pragma unroll
    for (int ks = 0; ks < 4; ks++) {
        int d0 = ks * 16 + 2 * tq;
        qa[ks][0] = qv0 ? *(const uint32_t*)&qp0[d0] : 0u;
        qa[ks][1] = qv1 ? *(const uint32_t*)&qp1[d0] : 0u;
        qa[ks][2] = qv0 ? *(const uint32_t*)&qp0[d0 + 8] : 0u;
        qa[ks][3] = qv1 ? *(const uint32_t*)&qp1[d0 + 8] : 0u;
    }

    float oacc[8][4];
#pragma unroll
    for (int i = 0; i < 8; i++)
#pragma unroll
        for (int j = 0; j < 4; j++) oacc[i][j] = 0.f;
    float m0 = -1e30f, m1 = -1e30f, l0 = 0.f, l1 = 0.f;

    uint32_t* pw = Ps + w * 16 * PST2;

    int vrow = (lane & 7) + ((lane >> 3) & 1) * 8;
    int vcol = (lane >> 4) * 8;
    uint32_t vs_base;
    asm("{ .reg .u64 t; cvta.to.shared.u64 t, %1; cvt.u32.u64 %0, t; }"
        : "=r"(vs_base) : "l"(Vs));
    uint32_t vaddr_t = vs_base + (uint32_t)(vrow * VST2 * 4 + vcol * 2);

    for (int kt = 0; kt < 25; kt++) {
        int k0 = kt * 64;
        __syncthreads();
#pragma unroll
        for (int i = 0; i < 4; i++) {
            int e = tid + i * 128;
            int r = e >> 3, c = e & 7;
            int ki = k0 + r;
            uint4 kv, vv;
            if (ki < NTOK) {
                kv = *(const uint4*)&Kb[(size_t)ki * HIDDEN + c * 8];
                vv = *(const uint4*)&Vb[(size_t)ki * HIDDEN + c * 8];
            } else {
                kv = make_uint4(0u, 0u, 0u, 0u);
                vv = kv;
            }
            *(uint4*)&Ks[r * KST2 + c * 4] = kv;
            *(uint4*)&Vs[r * VST2 + c * 4] = vv;
        }
        __syncthreads();

        float sacc[8][4];
#pragma unroll
        for (int nf = 0; nf < 8; nf++) {
            sacc[nf][0] = 0.f; sacc[nf][1] = 0.f; sacc[nf][2] = 0.f; sacc[nf][3] = 0.f;
            const uint32_t* krow = &Ks[(nf * 8 + g) * KST2];
#pragma unroll
            for (int ks = 0; ks < 4; ks++) {
                uint32_t b0 = krow[ks * 8 + tq];
                uint32_t b1 = krow[ks * 8 + tq + 4];
                mma16(sacc[nf], qa[ks][0], qa[ks][1], qa[ks][2], qa[ks][3], b0, b1);
            }
        }

        float mx0 = -1e30f, mx1 = -1e30f;
#pragma unroll
        for (int nf = 0; nf < 8; nf++) {
            int col0 = k0 + nf * 8 + 2 * tq;
            if (col0 >= NTOK)     { sacc[nf][0] = -1e30f; sacc[nf][2] = -1e30f; }
            if (col0 + 1 >= NTOK) { sacc[nf][1] = -1e30f; sacc[nf][3] = -1e30f; }
            mx0 = fmaxf(mx0, fmaxf(sacc[nf][0], sacc[nf][1]));
            mx1 = fmaxf(mx1, fmaxf(sacc[nf][2], sacc[nf][3]));
        }
        mx0 = fmaxf(mx0, __shfl_xor_sync(~0u, mx0, 1));
        mx0 = fmaxf(mx0, __shfl_xor_sync(~0u, mx0, 2));
        mx1 = fmaxf(mx1, __shfl_xor_sync(~0u, mx1, 1));
        mx1 = fmaxf(mx1, __shfl_xor_sync(~0u, mx1, 2));
        float mn0 = fmaxf(m0, mx0), mn1 = fmaxf(m1, mx1);
        float corr0 = __expf(m0 - mn0), corr1 = __expf(m1 - mn1);
        m0 = mn0; m1 = mn1;

        float ls0 = 0.f, ls1 = 0.f;
#pragma unroll
        for (int nf = 0; nf < 8; nf++) {
            float p0 = __expf(sacc[nf][0] - mn0);
            float p1 = __expf(sacc[nf][1] - mn0);
            float p2 = __expf(sacc[nf][2] - mn1);
            float p3 = __expf(sacc[nf][3] - mn1);
            ls0 += p0 + p1; ls1 += p2 + p3;
            pw[g * PST2 + nf * 4 + tq]       = pack2(p0, p1);
            pw[(g + 8) * PST2 + nf * 4 + tq] = pack2(p2, p3);
        }
        ls0 += __shfl_xor_sync(~0u, ls0, 1);
        ls0 += __shfl_xor_sync(~0u, ls0, 2);
        ls1 += __shfl_xor_sync(~0u, ls1, 1);
        ls1 += __shfl_xor_sync(~0u, ls1, 2);
        l0 = l0 * corr0 + ls0;
        l1 = l1 * corr1 + ls1;
#pragma unroll
        for (int nf2 = 0; nf2 < 8; nf2++) {
            oacc[nf2][0] *= corr0; oacc[nf2][1] *= corr0;
            oacc[nf2][2] *= corr1; oacc[nf2][3] *= corr1;
        }
        __syncwarp();

#pragma unroll
        for (int ks = 0; ks < 4; ks++) {
            uint32_t a0 = pw[g * PST2 + ks * 8 + tq];
            uint32_t a1 = pw[(g + 8) * PST2 + ks * 8 + tq];
            uint32_t a2 = pw[g * PST2 + ks * 8 + tq + 4];
            uint32_t a3 = pw[(g + 8) * PST2 + ks * 8 + tq + 4];
#pragma unroll
            for (int nfp = 0; nfp < 4; nfp++) {
                uint32_t addr = vaddr_t + (uint32_t)(ks * 16 * VST2 * 4 + nfp * 32);
                uint32_t v0, v1, v2, v3;
                asm volatile(
                    "ldmatrix.sync.aligned.m8n8.x4.trans.shared.b16 {%0,%1,%2,%3}, [%4];"
                    : "=r"(v0), "=r"(v1), "=r"(v2), "=r"(v3) : "r"(addr));
                mma16(oacc[nfp * 2],     a0, a1, a2, a3, v0, v1);
                mma16(oacc[nfp * 2 + 1], a0, a1, a2, a3, v2, v3);
            }
        }
        __syncwarp();
    }

    float inv0 = 1.f / l0, inv1 = 1.f / l1;
    __half* Ob = O + (size_t)b * NTOK * HIDDEN + h * HEADD;
#pragma unroll
    for (int nf2 = 0; nf2 < 8; nf2++) {
        int d0 = nf2 * 8 + 2 * tq;
        if (qv0)
            *(uint32_t*)&Ob[(size_t)qrow0 * HIDDEN + d0] =
                pack2(oacc[nf2][0] * inv0, oacc[nf2][1] * inv0);
        if (qv1)
            *(uint32_t*)&Ob[(size_t)qrow1 * HIDDEN + d0] =
                pack2(oacc[nf2][2] * inv1, oacc[nf2][3] * inv1);
    }
}

// ---------------- host orchestration ----------------
extern "C" void kernel_launch(void* const* d_in, const int* in_sizes, int n_in,
                              void* d_out, int out_size) {
    (void)in_sizes; (void)n_in; (void)out_size;
    const float* px      = (const float*)d_in[0];
    const float* patch_w = (const float*)d_in[1];
    const float* patch_b = (const float*)d_in[2];
    const float* ln1g = (const float*)d_in[3];
    const float* ln1b = (const float*)d_in[4];
    const float* qw = (const float*)d_in[5];
    const float* qb = (const float*)d_in[6];
    const float* kw = (const float*)d_in[7];
    const float* kb = (const float*)d_in[8];
    const float* vw = (const float*)d_in[9];
    const float* vb = (const float*)d_in[10];
    const float* pw = (const float*)d_in[11];
    const float* pb = (const float*)d_in[12];
    const float* ln2g = (const float*)d_in[13];
    const float* ln2b = (const float*)d_in[14];
    const float* fc1w = (const float*)d_in[15];
    const float* fc1b = (const float*)d_in[16];
    const float* fc2w = (const float*)d_in[17];
    const float* fc2b = (const float*)d_in[18];
    const float* lnfg = (const float*)d_in[19];
    const float* lnfb = (const float*)d_in[20];
    float* out = (float*)d_out;

    void *ph, *pqh, *pkh, *pvh, *pxnh, *paoh, *pmlph, *pcolh, *pwrh;
    cudaGetSymbolAddress(&ph,  g_h);
    cudaGetSymbolAddress(&pqh, g_qh);
    cudaGetSymbolAddress(&pkh, g_kh);
    cudaGetSymbolAddress(&pvh, g_vh);
    cudaGetSymbolAddress(&pxnh, g_xnh);
    cudaGetSymbolAddress(&paoh, g_aoh);
    cudaGetSymbolAddress(&pmlph, g_mlph);
    cudaGetSymbolAddress(&pcolh, g_colh);
    cudaGetSymbolAddress(&pwrh, g_wrh);
    float*  h    = (float*)ph;
    __half* qh   = (__half*)pqh;
    __half* kh   = (__half*)pkh;
    __half* vh   = (__half*)pvh;
    __half* xnh  = (__half*)pxnh;
    __half* aoh  = (__half*)paoh;
    __half* mlph = (__half*)pmlph;
    __half* colh = (__half*)pcolh;
    __half* wrh  = (__half*)pwrh;

    cudaFuncSetAttribute(tgemm<0>, cudaFuncAttributeMaxDynamicSharedMemorySize, GEMM_SMEM);
    cudaFuncSetAttribute(tgemm<1>, cudaFuncAttributeMaxDynamicSharedMemorySize, GEMM_SMEM);
    cudaFuncSetAttribute(tgemm<2>, cudaFuncAttributeMaxDynamicSharedMemorySize, GEMM_SMEM);
    cudaFuncSetAttribute(tgemm<3>, cudaFuncAttributeMaxDynamicSharedMemorySize, GEMM_SMEM);

    // patch embed
    im2col_k<<<(ROWS * PATCH_K + 255) / 256, 256>>>(px, colh);
    round4_k<<<(HIDDEN * PATCH_K / 4 + 255) / 256, 256>>>(patch_w, wrh, HIDDEN * PATCH_K / 4);
    tgemm<0><<<dim3(HIDDEN / 128, 25), 256, GEMM_SMEM>>>(
        colh, wrh, wrh, wrh, patch_b, patch_b, patch_b,
        nullptr, h, h, h, ROWS, HIDDEN, PATCH_K);

    for (int l = 0; l < LAYERS; l++) {
        size_t wo = (size_t)l * HIDDEN * HIDDEN;
        size_t bo = (size_t)l * HIDDEN;
        round_layer_k<<<(3 * MEG + 255) / 256, 256>>>(
            qw + wo, kw + wo, vw + wo, pw + wo,
            fc1w + (size_t)l * MLPD * HIDDEN, fc2w + (size_t)l * HIDDEN * MLPD, wrh);
        // attention block (RoPE fused into QKV epilogue)
        ln_k<true><<<ROWS, 256>>>(h, ln1g + bo, ln1b + bo, xnh);
        tgemm<3><<<dim3(24, 25), 256, GEMM_SMEM>>>(
            xnh, wrh, wrh + MEG, wrh + 2 * MEG, qb + bo, kb + bo, vb + bo,
            nullptr, (float*)qh, (float*)kh, (float*)vh, ROWS, HIDDEN, HIDDEN);
        attn_h<<<dim3(25, BATCH * HEADS), 128>>>(qh, kh, vh, aoh);
        tgemm<2><<<dim3(8, 25), 256, GEMM_SMEM>>>(
            aoh, wrh + 3 * MEG, wrh, wrh, pb + bo, pb + bo, pb + bo,
            h, h, h, h, ROWS, HIDDEN, HIDDEN);
        // MLP block
        ln_k<true><<<ROWS, 256>>>(h, ln2g + bo, ln2b + bo, xnh);
        tgemm<1><<<dim3(MLPD / 128, 25), 256, GEMM_SMEM>>>(
            xnh, wrh + 4 * MEG, wrh, wrh, fc1b + (size_t)l * MLPD, fc1b, fc1b,
            nullptr, (float*)mlph, (float*)mlph, (float*)mlph, ROWS, MLPD, HIDDEN);
        tgemm<2><<<dim3(8, 25), 256, GEMM_SMEM>>>(
            mlph, wrh + 8 * MEG, wrh, wrh, fc2b + bo, fc2b, fc2b,
            h, h, h, h, ROWS, HIDDEN, MLPD);
    }

    ln_k<false><<<ROWS, 256>>>(h, lnfg, lnfb, out);
}

// round 12
// speedup vs baseline: 1.1448x; 1.0207x over previous
#include <cuda_runtime.h>
#include <cuda_fp16.h>
#include <math.h>
#include <stdint.h>

#define HIDDEN 1024
#define HEADS 16
#define HEADD 64
#define LAYERS 4
#define MLPD 4096
#define NTOK 1568
#define BATCH 2
#define ROWS (BATCH * NTOK)          // 3136
#define PATCH_K 1536                 // 3*2*16*16
#define MEG (1 << 20)

// ---------------- scratch (device globals; no allocation allowed) ----------------
__device__ float  g_h  [ROWS * HIDDEN];
__device__ __half g_qh  [ROWS * HIDDEN];
__device__ __half g_kh  [ROWS * HIDDEN];
__device__ __half g_vh  [ROWS * HIDDEN];
__device__ __half g_xnh [ROWS * HIDDEN];
__device__ __half g_aoh [ROWS * HIDDEN];
__device__ __half g_mlph[ROWS * MLPD];
__device__ __half g_colh[ROWS * PATCH_K];
__device__ __half g_wrh [12 * MEG];   // per-layer fp16 weights (or patch embed)

// omega_i = 10000^(-i/10), i = 0..9
__constant__ float c_OM[10] = {
    1.0f, 0.3981071705534972f, 0.15848931924611134f, 0.06309573444801933f,
    0.025118864315095794f, 0.01f, 0.003981071705534973f, 0.001584893192461113f,
    0.0006309573444801932f, 0.00025118864315095795f
};

__device__ __forceinline__ uint32_t pack2(float a, float b) {
    __half2 h = __floats2half2_rn(a, b);
    return *(uint32_t*)&h;
}

// ---------------- weight conversion to fp16 ----------------
__global__ void round4_k(const float* __restrict__ in, __half* __restrict__ out, int n4) {
    int i = blockIdx.x * 256 + threadIdx.x;
    if (i >= n4) return;
    float4 v = ((const float4*)in)[i];
    ((uint2*)out)[i] = make_uint2(pack2(v.x, v.y), pack2(v.z, v.w));
}

__global__ void round_layer_k(const float* __restrict__ qw, const float* __restrict__ kw,
                              const float* __restrict__ vw, const float* __restrict__ pw,
                              const float* __restrict__ f1, const float* __restrict__ f2,
                              __half* __restrict__ out) {
    int i = blockIdx.x * 256 + threadIdx.x;      // float4 index, total 3*2^20
    if (i >= 3 * MEG) return;
    int u = i >> 18;
    const float* src;
    int base;
    if (u < 4) {
        src = (u == 0) ? qw : (u == 1) ? kw : (u == 2) ? vw : pw;
        base = i & 262143;
    } else if (u < 8) { src = f1; base = i - 4 * 262144; }
    else             { src = f2; base = i - 8 * 262144; }
    float4 v = ((const float4*)src)[base];
    ((uint2*)out)[i] = make_uint2(pack2(v.x, v.y), pack2(v.z, v.w));
}

// ---------------- im2col (stores fp16) ----------------
__global__ void im2col_k(const float* __restrict__ px, __half* __restrict__ col) {
    int idx = blockIdx.x * 256 + threadIdx.x;
    if (idx >= ROWS * PATCH_K) return;
    int m = idx / PATCH_K;
    int j = idx - m * PATCH_K;
    int c  = j >> 9;
    int r  = j & 511;
    int t  = r >> 8;
    int ph = (r >> 4) & 15;
    int pw = r & 15;
    int b = m / NTOK;
    int n = m - b * NTOK;
    int d  = n / 196;
    int rr = n - d * 196;
    int hy = rr / 14;
    int wx = rr - hy * 14;
    size_t src = ((size_t)((b * 16 + d * 2 + t) * 3 + c)) * (224 * 224)
               + (size_t)(hy * 16 + ph) * 224 + (wx * 16 + pw);
    col[idx] = __float2half_rn(px[src]);
}

// ---------------- fp16 tensor-core GEMM: cp.async 3-stage + ldmatrix ----------------
__device__ __forceinline__ void mma16(float* c, uint32_t a0, uint32_t a1, uint32_t a2,
                                      uint32_t a3, uint32_t b0, uint32_t b1) {
    asm volatile(
        "mma.sync.aligned.m16n8k16.row.col.f32.f16.f16.f32 "
        "{%0,%1,%2,%3},{%4,%5,%6,%7},{%8,%9},{%0,%1,%2,%3};"
        : "+f"(c[0]), "+f"(c[1]), "+f"(c[2]), "+f"(c[3])
        : "r"(a0), "r"(a1), "r"(a2), "r"(a3), "r"(b0), "r"(b1));
}
__device__ __forceinline__ void cpa16(uint32_t dst, const void* src, int szbytes) {
    asm volatile("cp.async.cg.shared.global [%0], [%1], 16, %2;"
                 :: "r"(dst), "l"(src), "r"(szbytes) : "memory");
}
#define CP_COMMIT() asm volatile("cp.async.commit_group;" ::: "memory")

#define RSU 36                         // u32 row stride
#define TILE_U32 (128 * RSU)           // 4608 u32 per operand tile
#define STAGE_BYTES (2 * TILE_U32 * 4) // 36864
#define GEMM_SMEM (3 * STAGE_BYTES)    // 110592

template <int MODE>
__global__ __launch_bounds__(256, 2) void tgemm(
    const __half* __restrict__ A,
    const __half* __restrict__ B0, const __half* __restrict__ B1, const __half* __restrict__ B2,
    const float* __restrict__ bias0, const float* __restrict__ bias1, const float* __restrict__ bias2,
    const float* __restrict__ res, float* __restrict__ C0, float* __restrict__ C1,
    float* __restrict__ C2, int M, int N, int K)
{
    extern __shared__ uint32_t smu[];
    uint32_t smbase;
    asm("{ .reg .u64 t; cvta.to.shared.u64 t, %1; cvt.u32.u64 %0, t; }"
        : "=r"(smbase) : "l"(smu));

    int m0 = blockIdx.y * 128;
    int n0 = blockIdx.x * 128;
    const __half* B = B0;
    const float* bias = bias0;
    float* C = C0;
    int wsel = 0;
    if (MODE == 3) {
        wsel = n0 >> 10;
        if (wsel == 1) { B = B1; bias = bias1; C = C1; }
        else if (wsel == 2) { B = B2; bias = bias2; C = C2; }
        n0 &= 1023;
    }

    const int t = threadIdx.x;
    const int warp = t >> 5, lane = t & 31;
    const int wm = (warp >> 2) * 64, wn = (warp & 3) * 32;
    const int g = lane >> 2, tig = lane & 3;

    const int asub = lane >> 3;
    const uint32_t a_off =
        (uint32_t)((wm + ((asub & 1) << 3) + (lane & 7)) * (RSU * 4) + (asub >> 1) * 16);
    const int bcol = wn + (lane & 7) + ((lane >> 4) << 3);
    const uint32_t b_off =
        (uint32_t)(bcol * (RSU * 4) + ((lane >> 3) & 1) * 16);

    float acc[4][4][4];
#pragma unroll
    for (int i = 0; i < 4; i++)
#pragma unroll
        for (int j = 0; j < 4; j++)
#pragma unroll
            for (int q = 0; q < 4; q++) acc[i][j][q] = 0.f;

    const int NC = K >> 6;

    auto stage_cp = [&](int s, int k0) {
        uint32_t sb = smbase + (uint32_t)s * STAGE_BYTES;
#pragma unroll
        for (int i = 0; i < 4; i++) {
            int e = t + i * 256;
            int row = e >> 3, c = e & 7;
            uint32_t off = (uint32_t)((row * RSU + c * 4) * 4);
            int gm = m0 + row;
            const __half* srcA = A + (size_t)(gm < M ? gm : 0) * K + k0 + c * 8;
            cpa16(sb + off, srcA, gm < M ? 16 : 0);
            int gn = n0 + row;
            const __half* srcB = B + (size_t)gn * K + k0 + c * 8;
            cpa16(sb + TILE_U32 * 4 + off, srcB, 16);
        }
    };

    auto compute = [&](int s) {
        uint32_t ab = smbase + (uint32_t)s * STAGE_BYTES;
        uint32_t bb = ab + TILE_U32 * 4;
#pragma unroll
        for (int gg = 0; gg < 4; gg++) {
            uint32_t pa[4][4];
#pragma unroll
            for (int fm = 0; fm < 4; fm++) {
                uint32_t addr = ab + a_off + (uint32_t)(fm * 16 * RSU * 4 + gg * 32);
                asm volatile(
                    "ldmatrix.sync.aligned.m8n8.x4.shared.b16 {%0,%1,%2,%3}, [%4];"
                    : "=r"(pa[fm][0]), "=r"(pa[fm][1]), "=r"(pa[fm][2]), "=r"(pa[fm][3])
                    : "r"(addr));
            }
            uint32_t pb[2][4];
#pragma unroll
            for (int p = 0; p < 2; p++) {
                uint32_t addr = bb + b_off + (uint32_t)(p * 16 * RSU * 4 + gg * 32);
                asm volatile(
                    "ldmatrix.sync.aligned.m8n8.x4.shared.b16 {%0,%1,%2,%3}, [%4];"
                    : "=r"(pb[p][0]), "=r"(pb[p][1]), "=r"(pb[p][2]), "=r"(pb[p][3])
                    : "r"(addr));
            }
#pragma unroll
            for (int fm = 0; fm < 4; fm++)
#pragma unroll
                for (int fn = 0; fn < 4; fn++)
                    mma16(acc[fm][fn], pa[fm][0], pa[fm][1], pa[fm][2], pa[fm][3],
                          pb[fn >> 1][(fn & 1) * 2], pb[fn >> 1][(fn & 1) * 2 + 1]);
        }
    };

    stage_cp(0, 0);
    CP_COMMIT();
    if (NC > 1) { stage_cp(1, 64); CP_COMMIT(); }

    for (int c = 0; c < NC; c++) {
        if (c + 1 < NC) asm volatile("cp.async.wait_group 1;" ::: "memory");
        else            asm volatile("cp.async.wait_group 0;" ::: "memory");
        __syncthreads();
        if (c + 2 < NC) { stage_cp((c + 2) % 3, (c + 2) << 6); CP_COMMIT(); }
        compute(c % 3);
    }

    // epilogue
    __half* Ch = (__half*)C;
#pragma unroll
    for (int fm = 0; fm < 4; fm++) {
        int r0 = m0 + wm + fm * 16 + g;
#pragma unroll
        for (int fn = 0; fn < 4; fn++) {
            int col = n0 + wn + fn * 8 + 2 * tig;
            float b0v = bias[col], b1v = bias[col + 1];
            float om0 = 0.f, om1 = 0.f;
            int axis = 3;
            if (MODE == 3 && wsel < 2) {
                int j = (col & 63) >> 1;
                if (j < 30) {
                    axis = j / 10;
                    int i = j - axis * 10;
                    int i0 = (2 * i) % 10, i1 = (2 * i + 1) % 10;
                    om0 = c_OM[i0]; om1 = c_OM[i1];
                }
            }
#pragma unroll
            for (int hrow = 0; hrow < 2; hrow++) {
                int r = r0 + hrow * 8;
                if (r >= M) continue;
                float v0 = acc[fm][fn][hrow * 2 + 0] + b0v;
                float v1 = acc[fm][fn][hrow * 2 + 1] + b1v;
                if (MODE == 1) {
                    v0 = 0.5f * v0 * (1.f + erff(v0 * 0.70710678118654752f));
                    v1 = 0.5f * v1 * (1.f + erff(v1 * 0.70710678118654752f));
                    *(uint32_t*)&Ch[(size_t)r * N + col] = pack2(v0, v1);
                } else if (MODE == 3) {
                    if (wsel < 2 && axis < 3) {
                        int n = r % NTOK;
                        int dpos = n / 196, rem = n - dpos * 196;
                        int pos = (axis == 0) ? dpos : (axis == 1) ? (rem / 14) : (rem % 14);
                        float fp = (float)pos;
                        float s0, c0, s1, c1;
                        __sincosf(fp * om0, &s0, &c0);
                        __sincosf(fp * om1, &s1, &c1);
                        float nv0 = v0 * c0 - v1 * s0;
                        float nv1 = v1 * c1 + v0 * s1;
                        v0 = nv0; v1 = nv1;
                    }
                    if (wsel == 0) { v0 *= 0.125f; v1 *= 0.125f; }
                    *(uint32_t*)&Ch[(size_t)r * N + col] = pack2(v0, v1);
                } else {
                    if (MODE == 2) {
                        const float* rr = &res[(size_t)r * N + col];
                        v0 += rr[0]; v1 += rr[1];
                    }
                    *(float2*)&C[(size_t)r * N + col] = make_float2(v0, v1);
                }
            }
        }
    }
}

// ---------------- LayerNorm (HALF_OUT: write fp16 for GEMM input) ----------------
template <bool HALF_OUT>
__global__ __launch_bounds__(256) void ln_k(
    const float* __restrict__ x, const float* __restrict__ g,
    const float* __restrict__ b, void* __restrict__ yv)
{
    __shared__ float red[8];
    __shared__ float stat[2];
    int row = blockIdx.x, tid = threadIdx.x;
    const float* xr = x + (size_t)row * HIDDEN;
    float v[4];
    float s = 0.f;
#pragma unroll
    for (int i = 0; i < 4; i++) { v[i] = xr[tid + i * 256]; s += v[i]; }
#pragma unroll
    for (int o = 16; o > 0; o >>= 1) s += __shfl_xor_sync(~0u, s, o);
    if ((tid & 31) == 0) red[tid >> 5] = s;
    __syncthreads();
    if (tid < 32) {
        float t = (tid < 8) ? red[tid] : 0.f;
#pragma unroll
        for (int o = 4; o > 0; o >>= 1) t += __shfl_xor_sync(~0u, t, o);
        if (tid == 0) stat[0] = t * (1.f / HIDDEN);
    }
    __syncthreads();
    float mu = stat[0];
    float s2 = 0.f;
#pragma unroll
    for (int i = 0; i < 4; i++) { float d = v[i] - mu; s2 += d * d; }
#pragma unroll
    for (int o = 16; o > 0; o >>= 1) s2 += __shfl_xor_sync(~0u, s2, o);
    if ((tid & 31) == 0) red[tid >> 5] = s2;
    __syncthreads();
    if (tid < 32) {
        float t = (tid < 8) ? red[tid] : 0.f;
#pragma unroll
        for (int o = 4; o > 0; o >>= 1) t += __shfl_xor_sync(~0u, t, o);
        if (tid == 0) stat[1] = rsqrtf(t * (1.f / HIDDEN) + 1e-6f);
    }
    __syncthreads();
    float rs = stat[1];
#pragma unroll
    for (int i = 0; i < 4; i++) {
        int c = tid + i * 256;
        float o = (v[i] - mu) * rs * g[c] + b[c];
        if (HALF_OUT) ((__half*)yv)[(size_t)row * HIDDEN + c] = __float2half_rn(o);
        else          ((float*)yv)[(size_t)row * HIDDEN + c] = o;
    }
}

// ---------------- Flash attention: Q-tile 128, cp.async 3-stage K/V pipeline ------
// 256 threads (8 warps x 16 q rows). K/V tiles 64 keys x 64 halves, row stride 36 u32.
#define AKST 36
#define ASTG_U32 (2 * 64 * AKST)               // K tile + V tile per stage: 4608 u32
#define ATTN_SMEM ((3 * ASTG_U32 + 128 * AKST) * 4)   // 73728 bytes

__global__ __launch_bounds__(256, 2) void attn_h(
    const __half* __restrict__ Q, const __half* __restrict__ K,
    const __half* __restrict__ V, __half* __restrict__ O)
{
    extern __shared__ uint32_t smu[];
    uint32_t smb;
    asm("{ .reg .u64 t; cvta.to.shared.u64 t, %1; cvt.u32.u64 %0, t; }"
        : "=r"(smb) : "l"(smu));

    int b = blockIdx.y >> 4, h = blockIdx.y & 15;
    int q0 = blockIdx.x * 128;
    int tid = threadIdx.x, w = tid >> 5, lane = tid & 31;
    int g = lane >> 2, tq = lane & 3;

    const __half* Qb = Q + (size_t)b * NTOK * HIDDEN + h * HEADD;
    const __half* Kb = K + (size_t)b * NTOK * HIDDEN + h * HEADD;
    const __half* Vb = V + (size_t)b * NTOK * HIDDEN + h * HEADD;

    uint32_t qa[4][4];
    int qrow0 = q0 + w * 16 + g;
    int qrow1 = qrow0 + 8;
    bool qv0 = qrow0 < NTOK, qv1 = qrow1 < NTOK;
    const __half* qp0 = Qb + (size_t)qrow0 * HIDDEN;
    const __half* qp1 = Qb + (size_t)qrow1 * HIDDEN;
#pragma unroll
    for (int ks = 0; ks < 4; ks++) {
        int d0 = ks * 16 + 2 * tq;
        qa[ks][0] = qv0 ? *(const uint32_t*)&qp0[d0] : 0u;
        qa[ks][1] = qv1 ? *(const uint32_t*)&qp1[d0] : 0u;
        qa[ks][2] = qv0 ? *(const uint32_t*)&qp0[d0 + 8] : 0u;
        qa[ks][3] = qv1 ? *(const uint32_t*)&qp1[d0 + 8] : 0u;
    }

    float oacc[8][4];
#pragma unroll
    for (int i = 0; i < 8; i++)
#pragma unroll
        for (int j = 0; j < 4; j++) oacc[i][j] = 0.f;
    float m0 = -1e30f, m1 = -1e30f, l0 = 0.f, l1 = 0.f;

    uint32_t* pw = smu + 3 * ASTG_U32 + w * 16 * AKST;

    int vrow = (lane & 7) + ((lane >> 3) & 1) * 8;
    int vcol = (lane >> 4) * 8;
    uint32_t vaddr_base = (uint32_t)(vrow * AKST * 4 + vcol * 2);

    auto stage_kv = [&](int s, int kt) {
        int k0 = kt * 64;
        uint32_t base = smb + (uint32_t)(s * ASTG_U32 * 4);
#pragma unroll
        for (int i = 0; i < 2; i++) {
            int e = tid + i * 256;               // 0..511
            int r = e >> 3, c = e & 7;
            int ki = k0 + r;
            int ok = (ki < NTOK) ? 16 : 0;
            size_t ro = (size_t)(ki < NTOK ? ki : 0) * HIDDEN + c * 8;
            uint32_t off = (uint32_t)((r * AKST + c * 4) * 4);
            cpa16(base + off, Kb + ro, ok);
            cpa16(base + (uint32_t)(64 * AKST * 4) + off, Vb + ro, ok);
        }
    };

    stage_kv(0, 0);
    CP_COMMIT();
    stage_kv(1, 1);
    CP_COMMIT();

    for (int kt = 0; kt < 25; kt++) {
        if (kt < 24) asm volatile("cp.async.wait_group 1;" ::: "memory");
        else         asm volatile("cp.async.wait_group 0;" ::: "memory");
        __syncthreads();
        if (kt + 2 < 25) { stage_kv((kt + 2) % 3, kt + 2); CP_COMMIT(); }

        int s = kt % 3;
        int k0 = kt * 64;
        const uint32_t* Kst = smu + s * ASTG_U32;

        float sacc[8][4];
#pragma unroll
        for (int nf = 0; nf < 8; nf++) {
            sacc[nf][0] = 0.f; sacc[nf][1] = 0.f; sacc[nf][2] = 0.f; sacc[nf][3] = 0.f;
            const uint32_t* krow = &Kst[(nf * 8 + g) * AKST];
#pragma unroll
            for (int ks = 0; ks < 4; ks++) {
                uint32_t b0 = krow[ks * 8 + tq];
                uint32_t b1 = krow[ks * 8 + tq + 4];
                mma16(sacc[nf], qa[ks][0], qa[ks][1], qa[ks][2], qa[ks][3], b0, b1);
            }
        }

        float mx0 = -1e30f, mx1 = -1e30f;
#pragma unroll
        for (int nf = 0; nf < 8; nf++) {
            int col0 = k0 + nf * 8 + 2 * tq;
            if (col0 >= NTOK)     { sacc[nf][0] = -1e30f; sacc[nf][2] = -1e30f; }
            if (col0 + 1 >= NTOK) { sacc[nf][1] = -1e30f; sacc[nf][3] = -1e30f; }
            mx0 = fmaxf(mx0, fmaxf(sacc[nf][0], sacc[nf][1]));
            mx1 = fmaxf(mx1, fmaxf(sacc[nf][2], sacc[nf][3]));
        }
        mx0 = fmaxf(mx0, __shfl_xor_sync(~0u, mx0, 1));
        mx0 = fmaxf(mx0, __shfl_xor_sync(~0u, mx0, 2));
        mx1 = fmaxf(mx1, __shfl_xor_sync(~0u, mx1, 1));
        mx1 = fmaxf(mx1, __shfl_xor_sync(~0u, mx1, 2));
        float mn0 = fmaxf(m0, mx0), mn1 = fmaxf(m1, mx1);
        float corr0 = __expf(m0 - mn0), corr1 = __expf(m1 - mn1);
        m0 = mn0; m1 = mn1;

        float ls0 = 0.f, ls1 = 0.f;
#pragma unroll
        for (int nf = 0; nf < 8; nf++) {
            float p0 = __expf(sacc[nf][0] - mn0);
            float p1 = __expf(sacc[nf][1] - mn0);
            float p2 = __expf(sacc[nf][2] - mn1);
            float p3 = __expf(sacc[nf][3] - mn1);
            ls0 += p0 + p1; ls1 += p2 + p3;
            pw[g * AKST + nf * 4 + tq]       = pack2(p0, p1);
            pw[(g + 8) * AKST + nf * 4 + tq] = pack2(p2, p3);
        }
        ls0 += __shfl_xor_sync(~0u, ls0, 1);
        ls0 += __shfl_xor_sync(~0u, ls0, 2);
        ls1 += __shfl_xor_sync(~0u, ls1, 1);
        ls1 += __shfl_xor_sync(~0u, ls1, 2);
        l0 = l0 * corr0 + ls0;
        l1 = l1 * corr1 + ls1;
#pragma unroll
        for (int nf2 = 0; nf2 < 8; nf2++) {
            oacc[nf2][0] *= corr0; oacc[nf2][1] *= corr0;
            oacc[nf2][2] *= corr1; oacc[nf2][3] *= corr1;
        }
        __syncwarp();

        uint32_t vaddr_t = smb + (uint32_t)(s * ASTG_U32 * 4 + 64 * AKST * 4) + vaddr_base;
#pragma unroll
        for (int ks = 0; ks < 4; ks++) {
            uint32_t a0 = pw[g * AKST + ks * 8 + tq];
            uint32_t a1 = pw[(g + 8) * AKST + ks * 8 + tq];
            uint32_t a2 = pw[g * AKST + ks * 8 + tq + 4];
            uint32_t a3 = pw[(g + 8) * AKST + ks * 8 + tq + 4];
#pragma unroll
            for (int nfp = 0; nfp < 4; nfp++) {
                uint32_t addr = vaddr_t + (uint32_t)(ks * 16 * AKST * 4 + nfp * 32);
                uint32_t v0, v1, v2, v3;
                asm volatile(
                    "ldmatrix.sync.aligned.m8n8.x4.trans.shared.b16 {%0,%1,%2,%3}, [%4];"
                    : "=r"(v0), "=r"(v1), "=r"(v2), "=r"(v3) : "r"(addr));
                mma16(oacc[nfp * 2],     a0, a1, a2, a3, v0, v1);
                mma16(oacc[nfp * 2 + 1], a0, a1, a2, a3, v2, v3);
            }
        }
        __syncwarp();
    }

    float inv0 = 1.f / l0, inv1 = 1.f / l1;
    __half* Ob = O + (size_t)b * NTOK * HIDDEN + h * HEADD;
#pragma unroll
    for (int nf2 = 0; nf2 < 8; nf2++) {
        int d0 = nf2 * 8 + 2 * tq;
        if (qv0)
            *(uint32_t*)&Ob[(size_t)qrow0 * HIDDEN + d0] =
                pack2(oacc[nf2][0] * inv0, oacc[nf2][1] * inv0);
        if (qv1)
            *(uint32_t*)&Ob[(size_t)qrow1 * HIDDEN + d0] =
                pack2(oacc[nf2][2] * inv1, oacc[nf2][3] * inv1);
    }
}

// ---------------- host orchestration ----------------
extern "C" void kernel_launch(void* const* d_in, const int* in_sizes, int n_in,
                              void* d_out, int out_size) {
    (void)in_sizes; (void)n_in; (void)out_size;
    const float* px      = (const float*)d_in[0];
    const float* patch_w = (const float*)d_in[1];
    const float* patch_b = (const float*)d_in[2];
    const float* ln1g = (const float*)d_in[3];
    const float* ln1b = (const float*)d_in[4];
    const float* qw = (const float*)d_in[5];
    const float* qb = (const float*)d_in[6];
    const float* kw = (const float*)d_in[7];
    const float* kb = (const float*)d_in[8];
    const float* vw = (const float*)d_in[9];
    const float* vb = (const float*)d_in[10];
    const float* pw = (const float*)d_in[11];
    const float* pb = (const float*)d_in[12];
    const float* ln2g = (const float*)d_in[13];
    const float* ln2b = (const float*)d_in[14];
    const float* fc1w = (const float*)d_in[15];
    const float* fc1b = (const float*)d_in[16];
    const float* fc2w = (const float*)d_in[17];
    const float* fc2b = (const float*)d_in[18];
    const float* lnfg = (const float*)d_in[19];
    const float* lnfb = (const float*)d_in[20];
    float* out = (float*)d_out;

    void *ph, *pqh, *pkh, *pvh, *pxnh, *paoh, *pmlph, *pcolh, *pwrh;
    cudaGetSymbolAddress(&ph,  g_h);
    cudaGetSymbolAddress(&pqh, g_qh);
    cudaGetSymbolAddress(&pkh, g_kh);
    cudaGetSymbolAddress(&pvh, g_vh);
    cudaGetSymbolAddress(&pxnh, g_xnh);
    cudaGetSymbolAddress(&paoh, g_aoh);
    cudaGetSymbolAddress(&pmlph, g_mlph);
    cudaGetSymbolAddress(&pcolh, g_colh);
    cudaGetSymbolAddress(&pwrh, g_wrh);
    float*  h    = (float*)ph;
    __half* qh   = (__half*)pqh;
    __half* kh   = (__half*)pkh;
    __half* vh   = (__half*)pvh;
    __half* xnh  = (__half*)pxnh;
    __half* aoh  = (__half*)paoh;
    __half* mlph = (__half*)pmlph;
    __half* colh = (__half*)pcolh;
    __half* wrh  = (__half*)pwrh;

    cudaFuncSetAttribute(tgemm<0>, cudaFuncAttributeMaxDynamicSharedMemorySize, GEMM_SMEM);
    cudaFuncSetAttribute(tgemm<1>, cudaFuncAttributeMaxDynamicSharedMemorySize, GEMM_SMEM);
    cudaFuncSetAttribute(tgemm<2>, cudaFuncAttributeMaxDynamicSharedMemorySize, GEMM_SMEM);
    cudaFuncSetAttribute(tgemm<3>, cudaFuncAttributeMaxDynamicSharedMemorySize, GEMM_SMEM);
    cudaFuncSetAttribute(attn_h, cudaFuncAttributeMaxDynamicSharedMemorySize, ATTN_SMEM);

    // patch embed
    im2col_k<<<(ROWS * PATCH_K + 255) / 256, 256>>>(px, colh);
    round4_k<<<(HIDDEN * PATCH_K / 4 + 255) / 256, 256>>>(patch_w, wrh, HIDDEN * PATCH_K / 4);
    tgemm<0><<<dim3(HIDDEN / 128, 25), 256, GEMM_SMEM>>>(
        colh, wrh, wrh, wrh, patch_b, patch_b, patch_b,
        nullptr, h, h, h, ROWS, HIDDEN, PATCH_K);

    for (int l = 0; l < LAYERS; l++) {
        size_t wo = (size_t)l * HIDDEN * HIDDEN;
        size_t bo = (size_t)l * HIDDEN;
        round_layer_k<<<(3 * MEG + 255) / 256, 256>>>(
            qw + wo, kw + wo, vw + wo, pw + wo,
            fc1w + (size_t)l * MLPD * HIDDEN, fc2w + (size_t)l * HIDDEN * MLPD, wrh);
        // attention block (RoPE fused into QKV epilogue)
        ln_k<true><<<ROWS, 256>>>(h, ln1g + bo, ln1b + bo, xnh);
        tgemm<3><<<dim3(24, 25), 256, GEMM_SMEM>>>(
            xnh, wrh, wrh + MEG, wrh + 2 * MEG, qb + bo, kb + bo, vb + bo,
            nullptr, (float*)qh, (float*)kh, (float*)vh, ROWS, HIDDEN, HIDDEN);
        attn_h<<<dim3(13, BATCH * HEADS), 256, ATTN_SMEM>>>(qh, kh, vh, aoh);
        tgemm<2><<<dim3(8, 25), 256, GEMM_SMEM>>>(
            aoh, wrh + 3 * MEG, wrh, wrh, pb + bo, pb + bo, pb + bo,
            h, h, h, h, ROWS, HIDDEN, HIDDEN);
        // MLP block
        ln_k<true><<<ROWS, 256>>>(h, ln2g + bo, ln2b + bo, xnh);
        tgemm<1><<<dim3(MLPD / 128, 25), 256, GEMM_SMEM>>>(
            xnh, wrh + 4 * MEG, wrh, wrh, fc1b + (size_t)l * MLPD, fc1b, fc1b,
            nullptr, (float*)mlph, (float*)mlph, (float*)mlph, ROWS, MLPD, HIDDEN);
        tgemm<2><<<dim3(8, 25), 256, GEMM_SMEM>>>(
            mlph, wrh + 8 * MEG, wrh, wrh, fc2b + bo, fc2b, fc2b,
            h, h, h, h, ROWS, HIDDEN, MLPD);
    }

    ln_k<false><<<ROWS, 256>>>(h, lnfg, lnfb, out);
}